// round 11
// baseline (speedup 1.0000x reference)
#include <cuda_runtime.h>
#include <cuda_fp16.h>
#include <math.h>
#include <stdint.h>

// ---------------- problem constants ----------------
#define BB 128      // batch
#define NN 49       // spatial tokens
#define CIN 2048
#define GG 256      // query groups
#define DD 768      // model dim
#define HH 8        // heads
#define HD 96       // head dim
#define FF 2048
#define NCLS 12547
#define DUP 50

// ---------------- asm helpers (sm_80+ features only) -------------------------
__device__ __forceinline__ uint32_t smem_u32(const void* p) {
    uint32_t a;
    asm("{ .reg .u64 t; cvta.to.shared.u64 t, %1; cvt.u32.u64 %0, t; }" : "=r"(a) : "l"(p));
    return a;
}
#define CP16(dst, src) \
    asm volatile("cp.async.cg.shared.global [%0], [%1], 16;" :: "r"(dst), "l"(src))
#define CP_COMMIT() asm volatile("cp.async.commit_group;" ::: "memory")
#define CP_WAIT(n)  asm volatile("cp.async.wait_group %0;" :: "n"(n) : "memory")
#define LDSM4(r, addr) \
    asm volatile("ldmatrix.sync.aligned.m8n8.x4.shared.b16 {%0,%1,%2,%3}, [%4];" \
                 : "=r"((r)[0]), "=r"((r)[1]), "=r"((r)[2]), "=r"((r)[3]) : "r"(addr))
#define MMA_F16(c, a, b0, b1) \
    asm volatile("mma.sync.aligned.m16n8k16.row.col.f32.f16.f16.f32 " \
                 "{%0,%1,%2,%3},{%4,%5,%6,%7},{%8,%9},{%0,%1,%2,%3};" \
                 : "+f"((c)[0]), "+f"((c)[1]), "+f"((c)[2]), "+f"((c)[3]) \
                 : "r"((a)[0]), "r"((a)[1]), "r"((a)[2]), "r"((a)[3]), "r"(b0), "r"(b1))

// ---------------- scratch (device globals) -----------------------------------
// fp32
__device__ float g_k    [BB * NN * DD];
__device__ float g_v    [BB * NN * DD];
__device__ float g_t1   [GG * DD];
__device__ float g_q    [GG * DD];
__device__ float g_oproj[BB * GG * DD];   // Wo out; later reused as h
__device__ float g_t2   [BB * GG * DD];
__device__ float g_ffn2 [BB * GG * DD];
// fp16 activation operands
__device__ __half g_xh [BB * NN * CIN];
__device__ __half g_mh [BB * NN * DD];
__device__ __half g_t1h[GG * DD];
__device__ __half g_aoh[BB * GG * DD];
__device__ __half g_t2h[BB * GG * DD];
__device__ __half g_ffh[BB * GG * FF];
// transposed fp16 weights: [N,K]
__device__ __half tWe[DD * CIN];
__device__ __half tWq[DD * DD];
__device__ __half tWk[DD * DD];
__device__ __half tWv[DD * DD];
__device__ __half tWo[DD * DD];
__device__ __half tW1[FF * DD];
__device__ __half tW2[DD * FF];

// ---------------- weight transpose: W[K,N] fp32 -> [N,K] fp16 ----------------
__global__ __launch_bounds__(256)
void transpose_half(const float* __restrict__ W, __half* __restrict__ o,
                    int K, int N)
{
    __shared__ float tile[32][33];
    const int tx = threadIdx.x & 31, ty = threadIdx.x >> 5;
    const int kb = blockIdx.y * 32, nb = blockIdx.x * 32;
    #pragma unroll
    for (int i = 0; i < 4; i++)
        tile[ty + i * 8][tx] = W[(size_t)(kb + ty + i * 8) * N + nb + tx];
    __syncthreads();
    #pragma unroll
    for (int i = 0; i < 4; i++) {
        const int n = nb + ty + i * 8, k = kb + tx;
        o[(size_t)n * K + k] = __float2half(tile[tx][ty + i * 8]);
    }
}

// ---------------- elementwise fp32 -> fp16 (for x) ---------------------------
__global__ __launch_bounds__(256)
void convert_half(const float* __restrict__ in, __half* __restrict__ out)
{
    const int i = (blockIdx.x * 256 + threadIdx.x) * 4;
    float4 v = *reinterpret_cast<const float4*>(in + i);
    __half2 a(__float2half(v.x), __float2half(v.y));
    __half2 b(__float2half(v.z), __float2half(v.w));
    *reinterpret_cast<__half2*>(out + i)     = a;
    *reinterpret_cast<__half2*>(out + i + 2) = b;
}

// ---------------- fp16 GEMM, 128x128 tile (small/medium M) -------------------
// C = act(alpha*(A @ B^T + bias));  A [M,K] fp16, B [N,K] fp16.
// BM=BN=128, BK=32; 4 warps x (64x64); 3-stage cp.async pipeline.
#define LDSH 40                      // smem row stride in halves (80B, conflict-free)
#define TILE_B (128 * LDSH * 2)      // 10240B per tile
#define STAGE_B (2 * TILE_B)         // 20480B per stage (A, B)
#define NSTAGE 3
#define GEMM_SMEM (NSTAGE * STAGE_B) // 61440B

template <int RELU, int HOUT>
__global__ __launch_bounds__(128, 2)
void tc_gemm(const __half* __restrict__ A, const __half* __restrict__ B,
             const float* __restrict__ bias,
             float* __restrict__ Cf, __half* __restrict__ Ch,
             int M, int N, int K, float alpha)
{
    extern __shared__ __half sm[];
    const uint32_t sb = smem_u32(sm);
    const int tid = threadIdx.x, wid = tid >> 5, lane = tid & 31;
    const int wm = wid & 1, wn = wid >> 1;             // warp tile: rows wm*64, cols wn*64
    const int m0 = blockIdx.y * 128, n0 = blockIdx.x * 128;
    const int nst = K >> 5;

    auto load_stage = [&](int s, int buf) {
        const int k0 = s << 5;
        const uint32_t d0 = sb + buf * STAGE_B;
        #pragma unroll
        for (int i = 0; i < 8; i++) {
            const int isA = (i < 4);
            const int c = (i & 3) * 128 + tid;
            const int row = c >> 2, part = c & 3;
            const __half* src = (isA ? A + (size_t)(m0 + row) * K
                                     : B + (size_t)(n0 + row) * K) + k0 + part * 8;
            const uint32_t dst = d0 + (isA ? 0 : TILE_B) + row * (LDSH * 2) + part * 16;
            CP16(dst, src);
        }
        CP_COMMIT();
    };

    float acc[4][8][4];
    #pragma unroll
    for (int i = 0; i < 4; i++)
        #pragma unroll
        for (int j = 0; j < 8; j++)
            #pragma unroll
            for (int q = 0; q < 4; q++) acc[i][j][q] = 0.f;

    load_stage(0, 0);
    if (1 < nst) load_stage(1, 1); else CP_COMMIT();

    const int a_r = (lane & 15), a_c8 = (lane >> 4) * 8;
    const int b_r = ((lane >> 4) & 1) * 8 + (lane & 7);
    const int b_c8 = ((lane >> 3) & 1) * 8;

    int buf = 0;
    #pragma unroll 1
    for (int s = 0; s < nst; s++) {
        const int pb = (buf + 2 >= NSTAGE) ? (buf + 2 - NSTAGE) : (buf + 2);
        if (s + 2 < nst) load_stage(s + 2, pb); else CP_COMMIT();
        CP_WAIT(2);
        __syncthreads();

        const uint32_t ab = sb + buf * STAGE_B;
        const uint32_t bb = ab + TILE_B;

        #pragma unroll
        for (int ks = 0; ks < 2; ks++) {
            const int kh = ks * 16;
            uint32_t fA[4][4], fB[4][4];
            #pragma unroll
            for (int i = 0; i < 4; i++) {
                const uint32_t off = ((wm * 64 + i * 16 + a_r) * LDSH + kh + a_c8) * 2;
                LDSM4(fA[i], ab + off);
            }
            #pragma unroll
            for (int j = 0; j < 4; j++) {
                const uint32_t off = ((wn * 64 + j * 16 + b_r) * LDSH + kh + b_c8) * 2;
                LDSM4(fB[j], bb + off);
            }
            #pragma unroll
            for (int n = 0; n < 8; n++) {
                const int j = n >> 1, h = (n & 1) * 2;
                const uint32_t b0 = fB[j][h], b1 = fB[j][h + 1];
                #pragma unroll
                for (int i = 0; i < 4; i++)
                    MMA_F16(acc[i][n], fA[i], b0, b1);
            }
        }
        __syncthreads();
        buf = (buf + 1 == NSTAGE) ? 0 : (buf + 1);
    }

    const int row0 = m0 + wm * 64 + (lane >> 2);
    const int col0 = n0 + wn * 64 + (lane & 3) * 2;
    #pragma unroll
    for (int i = 0; i < 4; i++) {
        #pragma unroll
        for (int j = 0; j < 8; j++) {
            const int r = row0 + i * 16;
            const int c = col0 + j * 8;
            const float b0 = bias[c], b1 = bias[c + 1];
            float v0 = alpha * (acc[i][j][0] + b0);
            float v1 = alpha * (acc[i][j][1] + b1);
            float v2 = alpha * (acc[i][j][2] + b0);
            float v3 = alpha * (acc[i][j][3] + b1);
            if (RELU) {
                v0 = fmaxf(v0, 0.f); v1 = fmaxf(v1, 0.f);
                v2 = fmaxf(v2, 0.f); v3 = fmaxf(v3, 0.f);
            }
            if (!HOUT) {
                *reinterpret_cast<float2*>(Cf + (size_t)r * N + c)       = make_float2(v0, v1);
                *reinterpret_cast<float2*>(Cf + (size_t)(r + 8) * N + c) = make_float2(v2, v3);
            } else {
                *reinterpret_cast<__half2*>(Ch + (size_t)r * N + c) =
                    __half2(__float2half(v0), __float2half(v1));
                *reinterpret_cast<__half2*>(Ch + (size_t)(r + 8) * N + c) =
                    __half2(__float2half(v2), __float2half(v3));
            }
        }
    }
}

// ---------------- fp16 GEMM, 256x128 tile (big M) ----------------------------
// Cuts L2->SMEM traffic 25% vs 128x128 (traffic ~ 1/BM + 1/BN).
// 8 warps x (64x64); 4-stage cp.async pipeline; 1 CTA/SM.  M%256==0.
#define BIG_A_B (256 * LDSH * 2)         // 20480B
#define BIG_STAGE (BIG_A_B + TILE_B)     // 30720B per stage (A 256 rows, B 128 rows)
#define BIG_NSTAGE 4
#define GEMM_SMEM_BIG (BIG_NSTAGE * BIG_STAGE)  // 122880B

template <int RELU, int HOUT>
__global__ __launch_bounds__(256, 1)
void tc_gemm_big(const __half* __restrict__ A, const __half* __restrict__ B,
                 const float* __restrict__ bias,
                 float* __restrict__ Cf, __half* __restrict__ Ch,
                 int M, int N, int K, float alpha)
{
    extern __shared__ __half sm[];
    const uint32_t sb = smem_u32(sm);
    const int tid = threadIdx.x, wid = tid >> 5, lane = tid & 31;
    const int wm = wid & 3, wn = wid >> 2;             // warp tile: rows wm*64, cols wn*64
    const int m0 = blockIdx.y * 256, n0 = blockIdx.x * 128;
    const int nst = K >> 5;

    // ---- async stage loader: 6 x 16B per thread (A 4, B 2) ----
    auto load_stage = [&](int s, int buf) {
        const int k0 = s << 5;
        const uint32_t d0 = sb + buf * BIG_STAGE;
        #pragma unroll
        for (int i = 0; i < 6; i++) {
            const int c = i * 256 + tid;                 // 0..1535
            if (c < 1024) {                              // A: 256 rows x 4 chunks
                const int row = c >> 2, part = c & 3;
                const __half* src = A + (size_t)(m0 + row) * K + k0 + part * 8;
                CP16(d0 + row * (LDSH * 2) + part * 16, src);
            } else {                                     // B: 128 rows x 4 chunks
                const int cc = c - 1024;
                const int row = cc >> 2, part = cc & 3;
                const __half* src = B + (size_t)(n0 + row) * K + k0 + part * 8;
                CP16(d0 + BIG_A_B + row * (LDSH * 2) + part * 16, src);
            }
        }
        CP_COMMIT();
    };

    float acc[4][8][4];
    #pragma unroll
    for (int i = 0; i < 4; i++)
        #pragma unroll
        for (int j = 0; j < 8; j++)
            #pragma unroll
            for (int q = 0; q < 4; q++) acc[i][j][q] = 0.f;

    load_stage(0, 0);
    load_stage(1, 1);
    load_stage(2, 2);       // K >= 768 here -> nst >= 24

    const int a_r = (lane & 15), a_c8 = (lane >> 4) * 8;
    const int b_r = ((lane >> 4) & 1) * 8 + (lane & 7);
    const int b_c8 = ((lane >> 3) & 1) * 8;

    int buf = 0;
    #pragma unroll 1
    for (int s = 0; s < nst; s++) {
        const int pb = (buf + 3 >= BIG_NSTAGE) ? (buf + 3 - BIG_NSTAGE) : (buf + 3);
        if (s + 3 < nst) load_stage(s + 3, pb); else CP_COMMIT();
        CP_WAIT(3);                  // uniform commits -> stage s resident
        __syncthreads();

        const uint32_t ab = sb + buf * BIG_STAGE;
        const uint32_t bb = ab + BIG_A_B;

        #pragma unroll
        for (int ks = 0; ks < 2; ks++) {
            const int kh = ks * 16;
            uint32_t fA[4][4], fB[4][4];
            #pragma unroll
            for (int i = 0; i < 4; i++) {
                const uint32_t off = ((wm * 64 + i * 16 + a_r) * LDSH + kh + a_c8) * 2;
                LDSM4(fA[i], ab + off);
            }
            #pragma unroll
            for (int j = 0; j < 4; j++) {
                const uint32_t off = ((wn * 64 + j * 16 + b_r) * LDSH + kh + b_c8) * 2;
                LDSM4(fB[j], bb + off);
            }
            #pragma unroll
            for (int n = 0; n < 8; n++) {
                const int j = n >> 1, h = (n & 1) * 2;
                const uint32_t b0 = fB[j][h], b1 = fB[j][h + 1];
                #pragma unroll
                for (int i = 0; i < 4; i++)
                    MMA_F16(acc[i][n], fA[i], b0, b1);
            }
        }
        __syncthreads();
        buf = (buf + 1 == BIG_NSTAGE) ? 0 : (buf + 1);
    }

    const int row0 = m0 + wm * 64 + (lane >> 2);
    const int col0 = n0 + wn * 64 + (lane & 3) * 2;
    #pragma unroll
    for (int i = 0; i < 4; i++) {
        #pragma unroll
        for (int j = 0; j < 8; j++) {
            const int r = row0 + i * 16;
            const int c = col0 + j * 8;
            const float b0 = bias[c], b1 = bias[c + 1];
            float v0 = alpha * (acc[i][j][0] + b0);
            float v1 = alpha * (acc[i][j][1] + b1);
            float v2 = alpha * (acc[i][j][2] + b0);
            float v3 = alpha * (acc[i][j][3] + b1);
            if (RELU) {
                v0 = fmaxf(v0, 0.f); v1 = fmaxf(v1, 0.f);
                v2 = fmaxf(v2, 0.f); v3 = fmaxf(v3, 0.f);
            }
            if (!HOUT) {
                *reinterpret_cast<float2*>(Cf + (size_t)r * N + c)       = make_float2(v0, v1);
                *reinterpret_cast<float2*>(Cf + (size_t)(r + 8) * N + c) = make_float2(v2, v3);
            } else {
                *reinterpret_cast<__half2*>(Ch + (size_t)r * N + c) =
                    __half2(__float2half(v0), __float2half(v1));
                *reinterpret_cast<__half2*>(Ch + (size_t)(r + 8) * N + c) =
                    __half2(__float2half(v2), __float2half(v3));
            }
        }
    }
}

// ---------------- LayerNorm over D=768 (optional fp16 side output) -----------
__global__ __launch_bounds__(256)
void ln_kernel(const float* __restrict__ a, const float* __restrict__ r,
               const float* __restrict__ gamma, const float* __restrict__ beta,
               float* __restrict__ out, __half* __restrict__ oh, int mode)
{
    const int row = blockIdx.x;
    const int t = threadIdx.x;
    const float* ap = a + (size_t)row * DD;

    float x[3];
    #pragma unroll
    for (int j = 0; j < 3; j++) {
        const int idx = t + j * 256;
        float val = ap[idx];
        if (mode == 0)      val = 2.f * val;
        else if (mode == 1) val += r[(size_t)(row & (GG - 1)) * DD + idx];
        else                val += r[(size_t)row * DD + idx];
        x[j] = val;
    }
    float s1 = x[0] + x[1] + x[2];
    float s2 = x[0] * x[0] + x[1] * x[1] + x[2] * x[2];
    #pragma unroll
    for (int off = 16; off; off >>= 1) {
        s1 += __shfl_xor_sync(0xffffffffu, s1, off);
        s2 += __shfl_xor_sync(0xffffffffu, s2, off);
    }
    __shared__ float sh1[8], sh2[8];
    const int w = t >> 5, lane = t & 31;
    if (lane == 0) { sh1[w] = s1; sh2[w] = s2; }
    __syncthreads();
    float S1 = 0.f, S2 = 0.f;
    #pragma unroll
    for (int i = 0; i < 8; i++) { S1 += sh1[i]; S2 += sh2[i]; }
    const float mean = S1 * (1.f / (float)DD);
    const float var  = S2 * (1.f / (float)DD) - mean * mean;
    const float rstd = rsqrtf(var + 1e-5f);

    #pragma unroll
    for (int j = 0; j < 3; j++) {
        const int idx = t + j * 256;
        const float v = (x[j] - mean) * rstd * gamma[idx] + beta[idx];
        out[(size_t)row * DD + idx] = v;
        if (oh) oh[(size_t)row * DD + idx] = __float2half(v);
    }
}

// ---------------- fused cross-attention, fp16 output -------------------------
__global__ __launch_bounds__(256)
void attn_kernel(const float* __restrict__ q, const float* __restrict__ k,
                 const float* __restrict__ v, __half* __restrict__ oh)
{
    __shared__ float ks[NN][HD];
    __shared__ float vs[NN][HD];
    const int h = blockIdx.x, b = blockIdx.y;
    const int t = threadIdx.x;

    for (int i = t; i < NN * HD; i += 256) {
        const int n = i / HD, d = i % HD;
        const size_t gi = ((size_t)(b * NN + n)) * DD + h * HD + d;
        ks[n][d] = k[gi];
        vs[n][d] = v[gi];
    }
    __syncthreads();

    const int g = t;
    float4 qv[HD / 4];
    const float4* qp = reinterpret_cast<const float4*>(q + (size_t)g * DD + h * HD);
    #pragma unroll
    for (int i = 0; i < HD / 4; i++) qv[i] = qp[i];

    float s[NN];
    #pragma unroll 7
    for (int n = 0; n < NN; n++) {
        const float4* kp = reinterpret_cast<const float4*>(ks[n]);
        float acc = 0.f;
        #pragma unroll
        for (int i = 0; i < HD / 4; i++) {
            float4 kk = kp[i];
            acc += qv[i].x * kk.x + qv[i].y * kk.y + qv[i].z * kk.z + qv[i].w * kk.w;
        }
        s[n] = acc;
    }
    float m = -1e30f;
    #pragma unroll
    for (int n = 0; n < NN; n++) m = fmaxf(m, s[n]);
    float sum = 0.f;
    #pragma unroll
    for (int n = 0; n < NN; n++) { s[n] = __expf(s[n] - m); sum += s[n]; }
    const float inv = 1.f / sum;

    const size_t ob = ((size_t)(b * GG + g)) * DD + h * HD;
    #pragma unroll
    for (int d4 = 0; d4 < HD / 4; d4++) {
        float4 acc = {0.f, 0.f, 0.f, 0.f};
        #pragma unroll 7
        for (int n = 0; n < NN; n++) {
            const float p = s[n];
            float4 vv = *reinterpret_cast<const float4*>(&vs[n][d4 * 4]);
            acc.x += p * vv.x; acc.y += p * vv.y; acc.z += p * vv.z; acc.w += p * vv.w;
        }
        acc.x *= inv; acc.y *= inv; acc.z *= inv; acc.w *= inv;
        *reinterpret_cast<__half2*>(oh + ob + d4 * 4) =
            __half2(__float2half(acc.x), __float2half(acc.y));
        *reinterpret_cast<__half2*>(oh + ob + d4 * 4 + 2) =
            __half2(__float2half(acc.z), __float2half(acc.w));
    }
}

// ---------------- GroupFC ----------------------------------------------------
__global__ __launch_bounds__(256)
void groupfc_kernel(const float* __restrict__ h, const float* __restrict__ Wg,
                    const float* __restrict__ bg, float* __restrict__ out)
{
    const int g  = blockIdx.y;
    const int b0 = blockIdx.x * 64;
    __shared__ float hs[32][65];
    __shared__ float ws[32][65];
    const int t = threadIdx.x;
    const int tx = (t % 16) * 4;
    const int ty = (t / 16) * 4;
    float acc[4][4] = {};

    for (int d0 = 0; d0 < DD; d0 += 32) {
        for (int i = t; i < 64 * 32; i += 256) {
            const int bi = i / 32, di = i % 32;
            hs[di][bi] = h[((size_t)(b0 + bi) * GG + g) * DD + d0 + di];
        }
        for (int i = t; i < 32 * 64; i += 256) {
            const int di = i / 64, fi = i % 64;
            ws[di][fi] = (fi < DUP) ? Wg[((size_t)g * DD + d0 + di) * DUP + fi] : 0.f;
        }
        __syncthreads();
        #pragma unroll
        for (int d = 0; d < 32; d++) {
            float rh[4], rb[4];
            #pragma unroll
            for (int i = 0; i < 4; i++) rh[i] = hs[d][ty + i];
            #pragma unroll
            for (int j = 0; j < 4; j++) rb[j] = ws[d][tx + j];
            #pragma unroll
            for (int i = 0; i < 4; i++)
                #pragma unroll
                for (int j = 0; j < 4; j++)
                    acc[i][j] += rh[i] * rb[j];
        }
        __syncthreads();
    }
    #pragma unroll
    for (int i = 0; i < 4; i++) {
        #pragma unroll
        for (int j = 0; j < 4; j++) {
            const int f = tx + j;
            if (f < DUP) {
                const int c = g * DUP + f;
                if (c < NCLS)
                    out[(size_t)(b0 + ty + i) * NCLS + c] = acc[i][j] + bg[c];
            }
        }
    }
}

// ---------------- launch -----------------------------------------------------
static float* sym(const void* s) { void* p = nullptr; cudaGetSymbolAddress(&p, s); return (float*)p; }
static __half* symh(const void* s) { void* p = nullptr; cudaGetSymbolAddress(&p, s); return (__half*)p; }

extern "C" void kernel_launch(void* const* d_in, const int* in_sizes, int n_in,
                              void* d_out, int out_size)
{
    (void)in_sizes; (void)n_in; (void)out_size;
    const float* x      = (const float*)d_in[0];
    const float* We     = (const float*)d_in[1];
    const float* be     = (const float*)d_in[2];
    const float* query  = (const float*)d_in[3];
    const float* Wq     = (const float*)d_in[4];
    const float* bq     = (const float*)d_in[5];
    const float* Wk     = (const float*)d_in[6];
    const float* bk     = (const float*)d_in[7];
    const float* Wv     = (const float*)d_in[8];
    const float* bv     = (const float*)d_in[9];
    const float* Wo     = (const float*)d_in[10];
    const float* bo     = (const float*)d_in[11];
    const float* g1     = (const float*)d_in[12];
    const float* beta1  = (const float*)d_in[13];
    const float* g2     = (const float*)d_in[14];
    const float* beta2  = (const float*)d_in[15];
    const float* g3     = (const float*)d_in[16];
    const float* beta3  = (const float*)d_in[17];
    const float* W1     = (const float*)d_in[18];
    const float* b1     = (const float*)d_in[19];
    const float* W2     = (const float*)d_in[20];
    const float* b2     = (const float*)d_in[21];
    const float* Wg     = (const float*)d_in[22];
    const float* bg     = (const float*)d_in[23];
    float* out = (float*)d_out;

    float *p_k = sym(g_k), *p_v = sym(g_v), *p_t1 = sym(g_t1), *p_q = sym(g_q);
    float *p_oproj = sym(g_oproj), *p_t2 = sym(g_t2), *p_ffn2 = sym(g_ffn2);
    __half *p_xh = symh(g_xh), *p_mh = symh(g_mh), *p_t1h = symh(g_t1h);
    __half *p_aoh = symh(g_aoh), *p_t2h = symh(g_t2h), *p_ffh = symh(g_ffh);
    __half *pWe = symh(tWe), *pWq = symh(tWq), *pWk = symh(tWk), *pWv = symh(tWv);
    __half *pWo = symh(tWo), *pW1 = symh(tW1), *pW2 = symh(tW2);

    cudaFuncSetAttribute(tc_gemm<0, 0>, cudaFuncAttributeMaxDynamicSharedMemorySize, GEMM_SMEM);
    cudaFuncSetAttribute(tc_gemm<0, 1>, cudaFuncAttributeMaxDynamicSharedMemorySize, GEMM_SMEM);
    cudaFuncSetAttribute(tc_gemm<1, 1>, cudaFuncAttributeMaxDynamicSharedMemorySize, GEMM_SMEM);
    cudaFuncSetAttribute(tc_gemm_big<0, 0>, cudaFuncAttributeMaxDynamicSharedMemorySize, GEMM_SMEM_BIG);
    cudaFuncSetAttribute(tc_gemm_big<1, 1>, cudaFuncAttributeMaxDynamicSharedMemorySize, GEMM_SMEM_BIG);

    const float qscale = 0.10206207261596577f;  // 1/sqrt(96)

    // weight transpose -> fp16 [N,K]
    transpose_half<<<dim3(DD / 32, CIN / 32), 256>>>(We, pWe, CIN, DD);
    transpose_half<<<dim3(DD / 32, DD / 32), 256>>>(Wq, pWq, DD, DD);
    transpose_half<<<dim3(DD / 32, DD / 32), 256>>>(Wk, pWk, DD, DD);
    transpose_half<<<dim3(DD / 32, DD / 32), 256>>>(Wv, pWv, DD, DD);
    transpose_half<<<dim3(DD / 32, DD / 32), 256>>>(Wo, pWo, DD, DD);
    transpose_half<<<dim3(FF / 32, DD / 32), 256>>>(W1, pW1, DD, FF);
    transpose_half<<<dim3(DD / 32, FF / 32), 256>>>(W2, pW2, FF, DD);
    // x -> fp16
    convert_half<<<(BB * NN * CIN) / 1024, 256>>>(x, p_xh);

    // t1 = LN(2*query) (+fp16); q = (t1@Wq + bq)/sqrt(96)
    ln_kernel<<<GG, 256>>>(query, nullptr, g1, beta1, p_t1, p_t1h, 0);
    tc_gemm<0, 0><<<dim3(DD / 128, GG / 128), 128, GEMM_SMEM>>>(
        p_t1h, pWq, bq, p_q, nullptr, GG, DD, DD, qscale);

    // mem = relu(x @ We + be)  -> fp16 directly
    tc_gemm<1, 1><<<dim3(DD / 128, (BB * NN) / 128), 128, GEMM_SMEM>>>(
        p_xh, pWe, be, nullptr, p_mh, BB * NN, DD, CIN, 1.f);
    // k, v projections (fp32 out for attention)
    tc_gemm<0, 0><<<dim3(DD / 128, (BB * NN) / 128), 128, GEMM_SMEM>>>(
        p_mh, pWk, bk, p_k, nullptr, BB * NN, DD, DD, 1.f);
    tc_gemm<0, 0><<<dim3(DD / 128, (BB * NN) / 128), 128, GEMM_SMEM>>>(
        p_mh, pWv, bv, p_v, nullptr, BB * NN, DD, DD, 1.f);

    // fused attention -> fp16
    attn_kernel<<<dim3(HH, BB), 256>>>(p_q, p_k, p_v, p_aoh);

    // output projection + residual LN (t2 fp32 + fp16)  [256-row tiles]
    tc_gemm_big<0, 0><<<dim3(DD / 128, (BB * GG) / 256), 256, GEMM_SMEM_BIG>>>(
        p_aoh, pWo, bo, p_oproj, nullptr, BB * GG, DD, DD, 1.f);
    ln_kernel<<<BB * GG, 256>>>(p_oproj, p_t1, g2, beta2, p_t2, p_t2h, 1);

    // FFN: ff = relu(t2@W1+b1) -> fp16; ffn2 = ff@W2+b2 -> fp32  [256-row tiles]
    tc_gemm_big<1, 1><<<dim3(FF / 128, (BB * GG) / 256), 256, GEMM_SMEM_BIG>>>(
        p_t2h, pW1, b1, nullptr, p_ffh, BB * GG, FF, DD, 1.f);
    tc_gemm_big<0, 0><<<dim3(DD / 128, (BB * GG) / 256), 256, GEMM_SMEM_BIG>>>(
        p_ffh, pW2, b2, p_ffn2, nullptr, BB * GG, DD, FF, 1.f);
    ln_kernel<<<BB * GG, 256>>>(p_ffn2, p_t2, g3, beta3, p_oproj, nullptr, 2);

    // GroupFC
    groupfc_kernel<<<dim3(BB / 64, GG), 256>>>(p_oproj, Wg, bg, out);
}

// round 12
// speedup vs baseline: 1.1279x; 1.1279x over previous
#include <cuda_runtime.h>
#include <cuda_fp16.h>
#include <math.h>
#include <stdint.h>

// ---------------- problem constants ----------------
#define BB 128      // batch
#define NN 49       // spatial tokens
#define CIN 2048
#define GG 256      // query groups
#define DD 768      // model dim
#define HH 8        // heads
#define HD 96       // head dim
#define FF 2048
#define NCLS 12547
#define DUP 50

// ---------------- asm helpers (sm_80+ features only) -------------------------
__device__ __forceinline__ uint32_t smem_u32(const void* p) {
    uint32_t a;
    asm("{ .reg .u64 t; cvta.to.shared.u64 t, %1; cvt.u32.u64 %0, t; }" : "=r"(a) : "l"(p));
    return a;
}
#define CP16(dst, src) \
    asm volatile("cp.async.cg.shared.global [%0], [%1], 16;" :: "r"(dst), "l"(src))
#define CP_COMMIT() asm volatile("cp.async.commit_group;" ::: "memory")
#define CP_WAIT(n)  asm volatile("cp.async.wait_group %0;" :: "n"(n) : "memory")
#define LDSM4(r, addr) \
    asm volatile("ldmatrix.sync.aligned.m8n8.x4.shared.b16 {%0,%1,%2,%3}, [%4];" \
                 : "=r"((r)[0]), "=r"((r)[1]), "=r"((r)[2]), "=r"((r)[3]) : "r"(addr))
#define MMA_F16(c, a, b0, b1) \
    asm volatile("mma.sync.aligned.m16n8k16.row.col.f32.f16.f16.f32 " \
                 "{%0,%1,%2,%3},{%4,%5,%6,%7},{%8,%9},{%0,%1,%2,%3};" \
                 : "+f"((c)[0]), "+f"((c)[1]), "+f"((c)[2]), "+f"((c)[3]) \
                 : "r"((a)[0]), "r"((a)[1]), "r"((a)[2]), "r"((a)[3]), "r"(b0), "r"(b1))

// ---------------- scratch (device globals) -----------------------------------
// fp32
__device__ float g_k    [BB * NN * DD];
__device__ float g_v    [BB * NN * DD];
__device__ float g_t1   [GG * DD];
__device__ float g_q    [GG * DD];
__device__ float g_oproj[BB * GG * DD];   // Wo out; later reused as h
__device__ float g_t2   [BB * GG * DD];
__device__ float g_ffn2 [BB * GG * DD];
// fp16 activation operands
__device__ __half g_xh [BB * NN * CIN];
__device__ __half g_mh [BB * NN * DD];
__device__ __half g_t1h[GG * DD];
__device__ __half g_aoh[BB * GG * DD];
__device__ __half g_t2h[BB * GG * DD];
__device__ __half g_ffh[BB * GG * FF];
// transposed fp16 weights: [N,K]
__device__ __half tWe[DD * CIN];
__device__ __half tWq[DD * DD];
__device__ __half tWk[DD * DD];
__device__ __half tWv[DD * DD];
__device__ __half tWo[DD * DD];
__device__ __half tW1[FF * DD];
__device__ __half tW2[DD * FF];

// ---------------- weight transpose: W[K,N] fp32 -> [N,K] fp16 ----------------
__global__ __launch_bounds__(256)
void transpose_half(const float* __restrict__ W, __half* __restrict__ o,
                    int K, int N)
{
    __shared__ float tile[32][33];
    const int tx = threadIdx.x & 31, ty = threadIdx.x >> 5;
    const int kb = blockIdx.y * 32, nb = blockIdx.x * 32;
    #pragma unroll
    for (int i = 0; i < 4; i++)
        tile[ty + i * 8][tx] = W[(size_t)(kb + ty + i * 8) * N + nb + tx];
    __syncthreads();
    #pragma unroll
    for (int i = 0; i < 4; i++) {
        const int n = nb + ty + i * 8, k = kb + tx;
        o[(size_t)n * K + k] = __float2half(tile[tx][ty + i * 8]);
    }
}

// ---------------- elementwise fp32 -> fp16 (for x) ---------------------------
__global__ __launch_bounds__(256)
void convert_half(const float* __restrict__ in, __half* __restrict__ out)
{
    const int i = (blockIdx.x * 256 + threadIdx.x) * 4;
    float4 v = *reinterpret_cast<const float4*>(in + i);
    __half2 a(__float2half(v.x), __float2half(v.y));
    __half2 b(__float2half(v.z), __float2half(v.w));
    *reinterpret_cast<__half2*>(out + i)     = a;
    *reinterpret_cast<__half2*>(out + i + 2) = b;
}

// ---------------- fp16 single-pass tensor-core GEMM --------------------------
// C = act(alpha*(A @ B^T + bias));  A [M,K] fp16, B [N,K] fp16.
// BM=BN=128, BK=32; 4 warps x (64x64); 4-stage cp.async pipeline; 2 CTA/SM.
// M%128==0, N%128==0, K%32==0 (and K>=128 for the 3-deep prologue).
#define LDSH 40                      // smem row stride in halves (80B, conflict-free)
#define TILE_B (128 * LDSH * 2)      // 10240B per tile
#define STAGE_B (2 * TILE_B)         // 20480B per stage (A, B)
#define NSTAGE 4
#define GEMM_SMEM (NSTAGE * STAGE_B) // 81920B

template <int RELU, int HOUT>
__global__ __launch_bounds__(128, 2)
void tc_gemm(const __half* __restrict__ A, const __half* __restrict__ B,
             const float* __restrict__ bias,
             float* __restrict__ Cf, __half* __restrict__ Ch,
             int M, int N, int K, float alpha)
{
    extern __shared__ __half sm[];
    const uint32_t sb = smem_u32(sm);
    const int tid = threadIdx.x, wid = tid >> 5, lane = tid & 31;
    const int wm = wid & 1, wn = wid >> 1;             // warp tile: rows wm*64, cols wn*64
    const int m0 = blockIdx.y * 128, n0 = blockIdx.x * 128;
    const int nst = K >> 5;

    auto load_stage = [&](int s, int buf) {
        const int k0 = s << 5;
        const uint32_t d0 = sb + buf * STAGE_B;
        #pragma unroll
        for (int i = 0; i < 8; i++) {
            const int isA = (i < 4);
            const int c = (i & 3) * 128 + tid;
            const int row = c >> 2, part = c & 3;
            const __half* src = (isA ? A + (size_t)(m0 + row) * K
                                     : B + (size_t)(n0 + row) * K) + k0 + part * 8;
            const uint32_t dst = d0 + (isA ? 0 : TILE_B) + row * (LDSH * 2) + part * 16;
            CP16(dst, src);
        }
        CP_COMMIT();
    };

    float acc[4][8][4];
    #pragma unroll
    for (int i = 0; i < 4; i++)
        #pragma unroll
        for (int j = 0; j < 8; j++)
            #pragma unroll
            for (int q = 0; q < 4; q++) acc[i][j][q] = 0.f;

    // 3-deep prologue (K >= 128 always holds here: K is 768 or 2048)
    load_stage(0, 0);
    load_stage(1, 1);
    load_stage(2, 2);

    const int a_r = (lane & 15), a_c8 = (lane >> 4) * 8;
    const int b_r = ((lane >> 4) & 1) * 8 + (lane & 7);
    const int b_c8 = ((lane >> 3) & 1) * 8;

    int buf = 0;
    #pragma unroll 1
    for (int s = 0; s < nst; s++) {
        const int pb = (buf + 3 >= NSTAGE) ? (buf + 3 - NSTAGE) : (buf + 3);
        if (s + 3 < nst) load_stage(s + 3, pb); else CP_COMMIT();
        CP_WAIT(3);                     // uniform commits -> stage s resident
        __syncthreads();

        const uint32_t ab = sb + buf * STAGE_B;
        const uint32_t bb = ab + TILE_B;

        // hoist all 16 LDSMs for the full 32-K slice (max MLP), then 64 MMAs
        uint32_t fA[2][4][4], fB[2][4][4];
        #pragma unroll
        for (int ks = 0; ks < 2; ks++) {
            const int kh = ks * 16;
            #pragma unroll
            for (int i = 0; i < 4; i++) {
                const uint32_t off = ((wm * 64 + i * 16 + a_r) * LDSH + kh + a_c8) * 2;
                LDSM4(fA[ks][i], ab + off);
            }
            #pragma unroll
            for (int j = 0; j < 4; j++) {
                const uint32_t off = ((wn * 64 + j * 16 + b_r) * LDSH + kh + b_c8) * 2;
                LDSM4(fB[ks][j], bb + off);
            }
        }
        #pragma unroll
        for (int ks = 0; ks < 2; ks++) {
            #pragma unroll
            for (int n = 0; n < 8; n++) {
                const int j = n >> 1, h = (n & 1) * 2;
                const uint32_t b0 = fB[ks][j][h], b1 = fB[ks][j][h + 1];
                #pragma unroll
                for (int i = 0; i < 4; i++)
                    MMA_F16(acc[i][n], fA[ks][i], b0, b1);
            }
        }
        __syncthreads();
        buf = (buf + 1 == NSTAGE) ? 0 : (buf + 1);
    }

    // ---- epilogue ----
    const int row0 = m0 + wm * 64 + (lane >> 2);
    const int col0 = n0 + wn * 64 + (lane & 3) * 2;
    #pragma unroll
    for (int i = 0; i < 4; i++) {
        #pragma unroll
        for (int j = 0; j < 8; j++) {
            const int r = row0 + i * 16;
            const int c = col0 + j * 8;
            const float b0 = bias[c], b1 = bias[c + 1];
            float v0 = alpha * (acc[i][j][0] + b0);
            float v1 = alpha * (acc[i][j][1] + b1);
            float v2 = alpha * (acc[i][j][2] + b0);
            float v3 = alpha * (acc[i][j][3] + b1);
            if (RELU) {
                v0 = fmaxf(v0, 0.f); v1 = fmaxf(v1, 0.f);
                v2 = fmaxf(v2, 0.f); v3 = fmaxf(v3, 0.f);
            }
            if (!HOUT) {
                *reinterpret_cast<float2*>(Cf + (size_t)r * N + c)       = make_float2(v0, v1);
                *reinterpret_cast<float2*>(Cf + (size_t)(r + 8) * N + c) = make_float2(v2, v3);
            } else {
                *reinterpret_cast<__half2*>(Ch + (size_t)r * N + c) =
                    __half2(__float2half(v0), __float2half(v1));
                *reinterpret_cast<__half2*>(Ch + (size_t)(r + 8) * N + c) =
                    __half2(__float2half(v2), __float2half(v3));
            }
        }
    }
}

// ---------------- LayerNorm over D=768 (optional fp16 side output) -----------
__global__ __launch_bounds__(256)
void ln_kernel(const float* __restrict__ a, const float* __restrict__ r,
               const float* __restrict__ gamma, const float* __restrict__ beta,
               float* __restrict__ out, __half* __restrict__ oh, int mode)
{
    const int row = blockIdx.x;
    const int t = threadIdx.x;
    const float* ap = a + (size_t)row * DD;

    float x[3];
    #pragma unroll
    for (int j = 0; j < 3; j++) {
        const int idx = t + j * 256;
        float val = ap[idx];
        if (mode == 0)      val = 2.f * val;
        else if (mode == 1) val += r[(size_t)(row & (GG - 1)) * DD + idx];
        else                val += r[(size_t)row * DD + idx];
        x[j] = val;
    }
    float s1 = x[0] + x[1] + x[2];
    float s2 = x[0] * x[0] + x[1] * x[1] + x[2] * x[2];
    #pragma unroll
    for (int off = 16; off; off >>= 1) {
        s1 += __shfl_xor_sync(0xffffffffu, s1, off);
        s2 += __shfl_xor_sync(0xffffffffu, s2, off);
    }
    __shared__ float sh1[8], sh2[8];
    const int w = t >> 5, lane = t & 31;
    if (lane == 0) { sh1[w] = s1; sh2[w] = s2; }
    __syncthreads();
    float S1 = 0.f, S2 = 0.f;
    #pragma unroll
    for (int i = 0; i < 8; i++) { S1 += sh1[i]; S2 += sh2[i]; }
    const float mean = S1 * (1.f / (float)DD);
    const float var  = S2 * (1.f / (float)DD) - mean * mean;
    const float rstd = rsqrtf(var + 1e-5f);

    #pragma unroll
    for (int j = 0; j < 3; j++) {
        const int idx = t + j * 256;
        const float v = (x[j] - mean) * rstd * gamma[idx] + beta[idx];
        out[(size_t)row * DD + idx] = v;
        if (oh) oh[(size_t)row * DD + idx] = __float2half(v);
    }
}

// ---------------- fused cross-attention, fp16 output -------------------------
__global__ __launch_bounds__(256)
void attn_kernel(const float* __restrict__ q, const float* __restrict__ k,
                 const float* __restrict__ v, __half* __restrict__ oh)
{
    __shared__ float ks[NN][HD];
    __shared__ float vs[NN][HD];
    const int h = blockIdx.x, b = blockIdx.y;
    const int t = threadIdx.x;

    for (int i = t; i < NN * HD; i += 256) {
        const int n = i / HD, d = i % HD;
        const size_t gi = ((size_t)(b * NN + n)) * DD + h * HD + d;
        ks[n][d] = k[gi];
        vs[n][d] = v[gi];
    }
    __syncthreads();

    const int g = t;
    float4 qv[HD / 4];
    const float4* qp = reinterpret_cast<const float4*>(q + (size_t)g * DD + h * HD);
    #pragma unroll
    for (int i = 0; i < HD / 4; i++) qv[i] = qp[i];

    float s[NN];
    #pragma unroll 7
    for (int n = 0; n < NN; n++) {
        const float4* kp = reinterpret_cast<const float4*>(ks[n]);
        float acc = 0.f;
        #pragma unroll
        for (int i = 0; i < HD / 4; i++) {
            float4 kk = kp[i];
            acc += qv[i].x * kk.x + qv[i].y * kk.y + qv[i].z * kk.z + qv[i].w * kk.w;
        }
        s[n] = acc;
    }
    float m = -1e30f;
    #pragma unroll
    for (int n = 0; n < NN; n++) m = fmaxf(m, s[n]);
    float sum = 0.f;
    #pragma unroll
    for (int n = 0; n < NN; n++) { s[n] = __expf(s[n] - m); sum += s[n]; }
    const float inv = 1.f / sum;

    const size_t ob = ((size_t)(b * GG + g)) * DD + h * HD;
    #pragma unroll
    for (int d4 = 0; d4 < HD / 4; d4++) {
        float4 acc = {0.f, 0.f, 0.f, 0.f};
        #pragma unroll 7
        for (int n = 0; n < NN; n++) {
            const float p = s[n];
            float4 vv = *reinterpret_cast<const float4*>(&vs[n][d4 * 4]);
            acc.x += p * vv.x; acc.y += p * vv.y; acc.z += p * vv.z; acc.w += p * vv.w;
        }
        acc.x *= inv; acc.y *= inv; acc.z *= inv; acc.w *= inv;
        *reinterpret_cast<__half2*>(oh + ob + d4 * 4) =
            __half2(__float2half(acc.x), __float2half(acc.y));
        *reinterpret_cast<__half2*>(oh + ob + d4 * 4 + 2) =
            __half2(__float2half(acc.z), __float2half(acc.w));
    }
}

// ---------------- GroupFC ----------------------------------------------------
__global__ __launch_bounds__(256)
void groupfc_kernel(const float* __restrict__ h, const float* __restrict__ Wg,
                    const float* __restrict__ bg, float* __restrict__ out)
{
    const int g  = blockIdx.y;
    const int b0 = blockIdx.x * 64;
    __shared__ float hs[32][65];
    __shared__ float ws[32][65];
    const int t = threadIdx.x;
    const int tx = (t % 16) * 4;
    const int ty = (t / 16) * 4;
    float acc[4][4] = {};

    for (int d0 = 0; d0 < DD; d0 += 32) {
        for (int i = t; i < 64 * 32; i += 256) {
            const int bi = i / 32, di = i % 32;
            hs[di][bi] = h[((size_t)(b0 + bi) * GG + g) * DD + d0 + di];
        }
        for (int i = t; i < 32 * 64; i += 256) {
            const int di = i / 64, fi = i % 64;
            ws[di][fi] = (fi < DUP) ? Wg[((size_t)g * DD + d0 + di) * DUP + fi] : 0.f;
        }
        __syncthreads();
        #pragma unroll
        for (int d = 0; d < 32; d++) {
            float rh[4], rb[4];
            #pragma unroll
            for (int i = 0; i < 4; i++) rh[i] = hs[d][ty + i];
            #pragma unroll
            for (int j = 0; j < 4; j++) rb[j] = ws[d][tx + j];
            #pragma unroll
            for (int i = 0; i < 4; i++)
                #pragma unroll
                for (int j = 0; j < 4; j++)
                    acc[i][j] += rh[i] * rb[j];
        }
        __syncthreads();
    }
    #pragma unroll
    for (int i = 0; i < 4; i++) {
        #pragma unroll
        for (int j = 0; j < 4; j++) {
            const int f = tx + j;
            if (f < DUP) {
                const int c = g * DUP + f;
                if (c < NCLS)
                    out[(size_t)(b0 + ty + i) * NCLS + c] = acc[i][j] + bg[c];
            }
        }
    }
}

// ---------------- launch -----------------------------------------------------
static float* sym(const void* s) { void* p = nullptr; cudaGetSymbolAddress(&p, s); return (float*)p; }
static __half* symh(const void* s) { void* p = nullptr; cudaGetSymbolAddress(&p, s); return (__half*)p; }

extern "C" void kernel_launch(void* const* d_in, const int* in_sizes, int n_in,
                              void* d_out, int out_size)
{
    (void)in_sizes; (void)n_in; (void)out_size;
    const float* x      = (const float*)d_in[0];
    const float* We     = (const float*)d_in[1];
    const float* be     = (const float*)d_in[2];
    const float* query  = (const float*)d_in[3];
    const float* Wq     = (const float*)d_in[4];
    const float* bq     = (const float*)d_in[5];
    const float* Wk     = (const float*)d_in[6];
    const float* bk     = (const float*)d_in[7];
    const float* Wv     = (const float*)d_in[8];
    const float* bv     = (const float*)d_in[9];
    const float* Wo     = (const float*)d_in[10];
    const float* bo     = (const float*)d_in[11];
    const float* g1     = (const float*)d_in[12];
    const float* beta1  = (const float*)d_in[13];
    const float* g2     = (const float*)d_in[14];
    const float* beta2  = (const float*)d_in[15];
    const float* g3     = (const float*)d_in[16];
    const float* beta3  = (const float*)d_in[17];
    const float* W1     = (const float*)d_in[18];
    const float* b1     = (const float*)d_in[19];
    const float* W2     = (const float*)d_in[20];
    const float* b2     = (const float*)d_in[21];
    const float* Wg     = (const float*)d_in[22];
    const float* bg     = (const float*)d_in[23];
    float* out = (float*)d_out;

    float *p_k = sym(g_k), *p_v = sym(g_v), *p_t1 = sym(g_t1), *p_q = sym(g_q);
    float *p_oproj = sym(g_oproj), *p_t2 = sym(g_t2), *p_ffn2 = sym(g_ffn2);
    __half *p_xh = symh(g_xh), *p_mh = symh(g_mh), *p_t1h = symh(g_t1h);
    __half *p_aoh = symh(g_aoh), *p_t2h = symh(g_t2h), *p_ffh = symh(g_ffh);
    __half *pWe = symh(tWe), *pWq = symh(tWq), *pWk = symh(tWk), *pWv = symh(tWv);
    __half *pWo = symh(tWo), *pW1 = symh(tW1), *pW2 = symh(tW2);

    cudaFuncSetAttribute(tc_gemm<0, 0>, cudaFuncAttributeMaxDynamicSharedMemorySize, GEMM_SMEM);
    cudaFuncSetAttribute(tc_gemm<0, 1>, cudaFuncAttributeMaxDynamicSharedMemorySize, GEMM_SMEM);
    cudaFuncSetAttribute(tc_gemm<1, 1>, cudaFuncAttributeMaxDynamicSharedMemorySize, GEMM_SMEM);

    const float qscale = 0.10206207261596577f;  // 1/sqrt(96)

    // Launch order chosen so launch #5 (ncu -s 5 -c 1) is the embed tc_gemm.
    transpose_half<<<dim3(DD / 32, CIN / 32), 256>>>(We, pWe, CIN, DD);      // 0
    convert_half<<<(BB * NN * CIN) / 1024, 256>>>(x, p_xh);                  // 1
    transpose_half<<<dim3(DD / 32, DD / 32), 256>>>(Wq, pWq, DD, DD);        // 2
    ln_kernel<<<GG, 256>>>(query, nullptr, g1, beta1, p_t1, p_t1h, 0);       // 3
    tc_gemm<0, 0><<<dim3(DD / 128, GG / 128), 128, GEMM_SMEM>>>(             // 4
        p_t1h, pWq, bq, p_q, nullptr, GG, DD, DD, qscale);
    // mem = relu(x @ We + be) -> fp16   [PROFILED LAUNCH]
    tc_gemm<1, 1><<<dim3(DD / 128, (BB * NN) / 128), 128, GEMM_SMEM>>>(      // 5
        p_xh, pWe, be, nullptr, p_mh, BB * NN, DD, CIN, 1.f);

    transpose_half<<<dim3(DD / 32, DD / 32), 256>>>(Wk, pWk, DD, DD);        // 6
    transpose_half<<<dim3(DD / 32, DD / 32), 256>>>(Wv, pWv, DD, DD);        // 7
    tc_gemm<0, 0><<<dim3(DD / 128, (BB * NN) / 128), 128, GEMM_SMEM>>>(      // 8
        p_mh, pWk, bk, p_k, nullptr, BB * NN, DD, DD, 1.f);
    tc_gemm<0, 0><<<dim3(DD / 128, (BB * NN) / 128), 128, GEMM_SMEM>>>(      // 9
        p_mh, pWv, bv, p_v, nullptr, BB * NN, DD, DD, 1.f);

    attn_kernel<<<dim3(HH, BB), 256>>>(p_q, p_k, p_v, p_aoh);                // 10

    transpose_half<<<dim3(DD / 32, DD / 32), 256>>>(Wo, pWo, DD, DD);        // 11
    tc_gemm<0, 0><<<dim3(DD / 128, (BB * GG) / 128), 128, GEMM_SMEM>>>(      // 12
        p_aoh, pWo, bo, p_oproj, nullptr, BB * GG, DD, DD, 1.f);
    ln_kernel<<<BB * GG, 256>>>(p_oproj, p_t1, g2, beta2, p_t2, p_t2h, 1);   // 13

    transpose_half<<<dim3(FF / 32, DD / 32), 256>>>(W1, pW1, DD, FF);        // 14
    tc_gemm<1, 1><<<dim3(FF / 128, (BB * GG) / 128), 128, GEMM_SMEM>>>(      // 15
        p_t2h, pW1, b1, nullptr, p_ffh, BB * GG, FF, DD, 1.f);
    transpose_half<<<dim3(DD / 32, FF / 32), 256>>>(W2, pW2, FF, DD);        // 16
    tc_gemm<0, 0><<<dim3(DD / 128, (BB * GG) / 128), 128, GEMM_SMEM>>>(      // 17
        p_ffh, pW2, b2, p_ffn2, nullptr, BB * GG, DD, FF, 1.f);
    ln_kernel<<<BB * GG, 256>>>(p_ffn2, p_t2, g3, beta3, p_oproj, nullptr, 2); // 18

    groupfc_kernel<<<dim3(BB / 64, GG), 256>>>(p_oproj, Wg, bg, out);        // 19
}

// round 13
// speedup vs baseline: 1.1780x; 1.0445x over previous
#include <cuda_runtime.h>
#include <cuda_fp16.h>
#include <math.h>
#include <stdint.h>

// ---------------- problem constants ----------------
#define BB 128      // batch
#define NN 49       // spatial tokens
#define CIN 2048
#define GG 256      // query groups
#define DD 768      // model dim
#define HH 8        // heads
#define HD 96       // head dim
#define FF 2048
#define NCLS 12547
#define DUP 50
#define DKV 1536    // concat K|V projection width

// ---------------- asm helpers (sm_80+ features only) -------------------------
__device__ __forceinline__ uint32_t smem_u32(const void* p) {
    uint32_t a;
    asm("{ .reg .u64 t; cvta.to.shared.u64 t, %1; cvt.u32.u64 %0, t; }" : "=r"(a) : "l"(p));
    return a;
}
#define CP16(dst, src) \
    asm volatile("cp.async.cg.shared.global [%0], [%1], 16;" :: "r"(dst), "l"(src))
#define CP_COMMIT() asm volatile("cp.async.commit_group;" ::: "memory")
#define CP_WAIT(n)  asm volatile("cp.async.wait_group %0;" :: "n"(n) : "memory")
#define LDSM4(r, addr) \
    asm volatile("ldmatrix.sync.aligned.m8n8.x4.shared.b16 {%0,%1,%2,%3}, [%4];" \
                 : "=r"((r)[0]), "=r"((r)[1]), "=r"((r)[2]), "=r"((r)[3]) : "r"(addr))
#define MMA_F16(c, a, b0, b1) \
    asm volatile("mma.sync.aligned.m16n8k16.row.col.f32.f16.f16.f32 " \
                 "{%0,%1,%2,%3},{%4,%5,%6,%7},{%8,%9},{%0,%1,%2,%3};" \
                 : "+f"((c)[0]), "+f"((c)[1]), "+f"((c)[2]), "+f"((c)[3]) \
                 : "r"((a)[0]), "r"((a)[1]), "r"((a)[2]), "r"((a)[3]), "r"(b0), "r"(b1))

// ---------------- scratch (device globals) -----------------------------------
// fp32
__device__ float g_kv   [BB * NN * DKV];  // concat K|V projections
__device__ float g_t1   [GG * DD];
__device__ float g_q    [GG * DD];
__device__ float g_t2   [BB * GG * DD];
__device__ float g_h    [BB * GG * DD];   // final LN out (groupfc input)
__device__ float g_bkv  [DKV];            // concat bias bk|bv
// fp16 activation operands
__device__ __half g_xh [BB * NN * CIN];
__device__ __half g_mh [BB * NN * DD];
__device__ __half g_t1h[GG * DD];
__device__ __half g_aoh[BB * GG * DD];
__device__ __half g_oph[BB * GG * DD];    // Wo out (fp16)
__device__ __half g_t2h[BB * GG * DD];
__device__ __half g_ffh[BB * GG * FF];
__device__ __half g_f2h[BB * GG * DD];    // W2 out (fp16)
// transposed fp16 weights: [N,K]
__device__ __half tWe [DD * CIN];
__device__ __half tWq [DD * DD];
__device__ __half tWkv[DKV * DD];         // rows 0..767 = Wk^T, 768..1535 = Wv^T
__device__ __half tWo [DD * DD];
__device__ __half tW1 [FF * DD];
__device__ __half tW2 [DD * FF];

// ---------------- weight transpose: W[K,N] fp32 -> [N,K] fp16 ----------------
__global__ __launch_bounds__(256)
void transpose_half(const float* __restrict__ W, __half* __restrict__ o,
                    int K, int N)
{
    __shared__ float tile[32][33];
    const int tx = threadIdx.x & 31, ty = threadIdx.x >> 5;
    const int kb = blockIdx.y * 32, nb = blockIdx.x * 32;
    #pragma unroll
    for (int i = 0; i < 4; i++)
        tile[ty + i * 8][tx] = W[(size_t)(kb + ty + i * 8) * N + nb + tx];
    __syncthreads();
    #pragma unroll
    for (int i = 0; i < 4; i++) {
        const int n = nb + ty + i * 8, k = kb + tx;
        o[(size_t)n * K + k] = __float2half(tile[tx][ty + i * 8]);
    }
}

// ---------------- elementwise fp32 -> fp16 (for x) ---------------------------
__global__ __launch_bounds__(256)
void convert_half(const float* __restrict__ in, __half* __restrict__ out)
{
    const int i = (blockIdx.x * 256 + threadIdx.x) * 4;
    float4 v = *reinterpret_cast<const float4*>(in + i);
    __half2 a(__float2half(v.x), __float2half(v.y));
    __half2 b(__float2half(v.z), __float2half(v.w));
    *reinterpret_cast<__half2*>(out + i)     = a;
    *reinterpret_cast<__half2*>(out + i + 2) = b;
}

// ---------------- concat bk|bv ------------------------------------------------
__global__ void concat_bias(const float* __restrict__ bk, const float* __restrict__ bv,
                            float* __restrict__ o)
{
    const int i = blockIdx.x * 256 + threadIdx.x;
    if (i < DD) o[i] = bk[i];
    else if (i < DKV) o[i] = bv[i - DD];
}

// ---------------- fp16 single-pass tensor-core GEMM --------------------------
// C = act(alpha*(A @ B^T + bias));  A [M,K] fp16, B [N,K] fp16.
// BM=BN=128, BK=32; 4 warps x (64x64); 4-stage cp.async pipeline; 2 CTA/SM;
// single __syncthreads per K-iteration.  M%128==0, N%128==0, K%32==0, K>=128.
#define LDSH 40                      // smem row stride in halves (80B, conflict-free)
#define TILE_B (128 * LDSH * 2)      // 10240B per tile
#define STAGE_B (2 * TILE_B)         // 20480B per stage (A, B)
#define NSTAGE 4
#define GEMM_SMEM (NSTAGE * STAGE_B) // 81920B

template <int RELU, int HOUT>
__global__ __launch_bounds__(128, 2)
void tc_gemm(const __half* __restrict__ A, const __half* __restrict__ B,
             const float* __restrict__ bias,
             float* __restrict__ Cf, __half* __restrict__ Ch,
             int M, int N, int K, float alpha)
{
    extern __shared__ __half sm[];
    const uint32_t sb = smem_u32(sm);
    const int tid = threadIdx.x, wid = tid >> 5, lane = tid & 31;
    const int wm = wid & 1, wn = wid >> 1;             // warp tile: rows wm*64, cols wn*64
    const int m0 = blockIdx.y * 128, n0 = blockIdx.x * 128;
    const int nst = K >> 5;

    auto load_stage = [&](int s, int buf) {
        const int k0 = s << 5;
        const uint32_t d0 = sb + buf * STAGE_B;
        #pragma unroll
        for (int i = 0; i < 8; i++) {
            const int isA = (i < 4);
            const int c = (i & 3) * 128 + tid;
            const int row = c >> 2, part = c & 3;
            const __half* src = (isA ? A + (size_t)(m0 + row) * K
                                     : B + (size_t)(n0 + row) * K) + k0 + part * 8;
            const uint32_t dst = d0 + (isA ? 0 : TILE_B) + row * (LDSH * 2) + part * 16;
            CP16(dst, src);
        }
        CP_COMMIT();
    };

    float acc[4][8][4];
    #pragma unroll
    for (int i = 0; i < 4; i++)
        #pragma unroll
        for (int j = 0; j < 8; j++)
            #pragma unroll
            for (int q = 0; q < 4; q++) acc[i][j][q] = 0.f;

    // 3-deep prologue (K >= 128 always holds here)
    load_stage(0, 0);
    load_stage(1, 1);
    load_stage(2, 2);

    const int a_r = (lane & 15), a_c8 = (lane >> 4) * 8;
    const int b_r = ((lane >> 4) & 1) * 8 + (lane & 7);
    const int b_c8 = ((lane >> 3) & 1) * 8;

    int buf = 0;
    #pragma unroll 1
    for (int s = 0; s < nst; s++) {
        CP_WAIT(2);                     // uniform commits -> stage s resident
        __syncthreads();                // cross-warp visibility + buffer-reuse fence
        // prefetch s+3 into (buf+3)%4 == buffer consumed in iter s-1 (safe: sync above)
        const int pb = (buf + 3) & 3;
        if (s + 3 < nst) load_stage(s + 3, pb); else CP_COMMIT();

        const uint32_t ab = sb + buf * STAGE_B;
        const uint32_t bb = ab + TILE_B;

        uint32_t fA[2][4][4], fB[2][4][4];
        #pragma unroll
        for (int ks = 0; ks < 2; ks++) {
            const int kh = ks * 16;
            #pragma unroll
            for (int i = 0; i < 4; i++) {
                const uint32_t off = ((wm * 64 + i * 16 + a_r) * LDSH + kh + a_c8) * 2;
                LDSM4(fA[ks][i], ab + off);
            }
            #pragma unroll
            for (int j = 0; j < 4; j++) {
                const uint32_t off = ((wn * 64 + j * 16 + b_r) * LDSH + kh + b_c8) * 2;
                LDSM4(fB[ks][j], bb + off);
            }
        }
        #pragma unroll
        for (int ks = 0; ks < 2; ks++) {
            #pragma unroll
            for (int n = 0; n < 8; n++) {
                const int j = n >> 1, h = (n & 1) * 2;
                const uint32_t b0 = fB[ks][j][h], b1 = fB[ks][j][h + 1];
                #pragma unroll
                for (int i = 0; i < 4; i++)
                    MMA_F16(acc[i][n], fA[ks][i], b0, b1);
            }
        }
        buf = (buf + 1) & 3;
    }

    // ---- epilogue ----
    const int row0 = m0 + wm * 64 + (lane >> 2);
    const int col0 = n0 + wn * 64 + (lane & 3) * 2;
    #pragma unroll
    for (int i = 0; i < 4; i++) {
        #pragma unroll
        for (int j = 0; j < 8; j++) {
            const int r = row0 + i * 16;
            const int c = col0 + j * 8;
            const float b0 = bias[c], b1 = bias[c + 1];
            float v0 = alpha * (acc[i][j][0] + b0);
            float v1 = alpha * (acc[i][j][1] + b1);
            float v2 = alpha * (acc[i][j][2] + b0);
            float v3 = alpha * (acc[i][j][3] + b1);
            if (RELU) {
                v0 = fmaxf(v0, 0.f); v1 = fmaxf(v1, 0.f);
                v2 = fmaxf(v2, 0.f); v3 = fmaxf(v3, 0.f);
            }
            if (!HOUT) {
                *reinterpret_cast<float2*>(Cf + (size_t)r * N + c)       = make_float2(v0, v1);
                *reinterpret_cast<float2*>(Cf + (size_t)(r + 8) * N + c) = make_float2(v2, v3);
            } else {
                *reinterpret_cast<__half2*>(Ch + (size_t)r * N + c) =
                    __half2(__float2half(v0), __float2half(v1));
                *reinterpret_cast<__half2*>(Ch + (size_t)(r + 8) * N + c) =
                    __half2(__float2half(v2), __float2half(v3));
            }
        }
    }
}

// ---------------- LayerNorm over D=768 ---------------------------------------
// mode 0: x = 2*a32[row]               (fp32 in)
// mode 1: x = a16[row] + r[row%G]      (fp16 main in, fp32 residual)
// mode 2: x = a16[row] + r[row]        (fp16 main in, fp32 residual)
__global__ __launch_bounds__(256)
void ln_kernel(const float* __restrict__ a32, const __half* __restrict__ a16,
               const float* __restrict__ r,
               const float* __restrict__ gamma, const float* __restrict__ beta,
               float* __restrict__ out, __half* __restrict__ oh, int mode)
{
    const int row = blockIdx.x;
    const int t = threadIdx.x;

    float x[3];
    #pragma unroll
    for (int j = 0; j < 3; j++) {
        const int idx = t + j * 256;
        float val;
        if (mode == 0) {
            val = 2.f * a32[(size_t)row * DD + idx];
        } else {
            val = __half2float(a16[(size_t)row * DD + idx]);
            if (mode == 1) val += r[(size_t)(row & (GG - 1)) * DD + idx];
            else           val += r[(size_t)row * DD + idx];
        }
        x[j] = val;
    }
    float s1 = x[0] + x[1] + x[2];
    float s2 = x[0] * x[0] + x[1] * x[1] + x[2] * x[2];
    #pragma unroll
    for (int off = 16; off; off >>= 1) {
        s1 += __shfl_xor_sync(0xffffffffu, s1, off);
        s2 += __shfl_xor_sync(0xffffffffu, s2, off);
    }
    __shared__ float sh1[8], sh2[8];
    const int w = t >> 5, lane = t & 31;
    if (lane == 0) { sh1[w] = s1; sh2[w] = s2; }
    __syncthreads();
    float S1 = 0.f, S2 = 0.f;
    #pragma unroll
    for (int i = 0; i < 8; i++) { S1 += sh1[i]; S2 += sh2[i]; }
    const float mean = S1 * (1.f / (float)DD);
    const float var  = S2 * (1.f / (float)DD) - mean * mean;
    const float rstd = rsqrtf(var + 1e-5f);

    #pragma unroll
    for (int j = 0; j < 3; j++) {
        const int idx = t + j * 256;
        const float v = (x[j] - mean) * rstd * gamma[idx] + beta[idx];
        if (out) out[(size_t)row * DD + idx] = v;
        if (oh) oh[(size_t)row * DD + idx] = __float2half(v);
    }
}

// ---------------- fused cross-attention (kv concat layout), fp16 output ------
__global__ __launch_bounds__(256)
void attn_kernel(const float* __restrict__ q, const float* __restrict__ kv,
                 __half* __restrict__ oh)
{
    __shared__ float ks[NN][HD];
    __shared__ float vs[NN][HD];
    const int h = blockIdx.x, b = blockIdx.y;
    const int t = threadIdx.x;

    for (int i = t; i < NN * HD; i += 256) {
        const int n = i / HD, d = i % HD;
        const size_t gi = ((size_t)(b * NN + n)) * DKV + h * HD + d;
        ks[n][d] = kv[gi];
        vs[n][d] = kv[gi + DD];
    }
    __syncthreads();

    const int g = t;
    float4 qv[HD / 4];
    const float4* qp = reinterpret_cast<const float4*>(q + (size_t)g * DD + h * HD);
    #pragma unroll
    for (int i = 0; i < HD / 4; i++) qv[i] = qp[i];

    float s[NN];
    #pragma unroll 7
    for (int n = 0; n < NN; n++) {
        const float4* kp = reinterpret_cast<const float4*>(ks[n]);
        float acc = 0.f;
        #pragma unroll
        for (int i = 0; i < HD / 4; i++) {
            float4 kk = kp[i];
            acc += qv[i].x * kk.x + qv[i].y * kk.y + qv[i].z * kk.z + qv[i].w * kk.w;
        }
        s[n] = acc;
    }
    float m = -1e30f;
    #pragma unroll
    for (int n = 0; n < NN; n++) m = fmaxf(m, s[n]);
    float sum = 0.f;
    #pragma unroll
    for (int n = 0; n < NN; n++) { s[n] = __expf(s[n] - m); sum += s[n]; }
    const float inv = 1.f / sum;

    const size_t ob = ((size_t)(b * GG + g)) * DD + h * HD;
    #pragma unroll
    for (int d4 = 0; d4 < HD / 4; d4++) {
        float4 acc = {0.f, 0.f, 0.f, 0.f};
        #pragma unroll 7
        for (int n = 0; n < NN; n++) {
            const float p = s[n];
            float4 vv = *reinterpret_cast<const float4*>(&vs[n][d4 * 4]);
            acc.x += p * vv.x; acc.y += p * vv.y; acc.z += p * vv.z; acc.w += p * vv.w;
        }
        acc.x *= inv; acc.y *= inv; acc.z *= inv; acc.w *= inv;
        *reinterpret_cast<__half2*>(oh + ob + d4 * 4) =
            __half2(__float2half(acc.x), __float2half(acc.y));
        *reinterpret_cast<__half2*>(oh + ob + d4 * 4 + 2) =
            __half2(__float2half(acc.z), __float2half(acc.w));
    }
}

// ---------------- GroupFC ----------------------------------------------------
__global__ __launch_bounds__(256)
void groupfc_kernel(const float* __restrict__ h, const float* __restrict__ Wg,
                    const float* __restrict__ bg, float* __restrict__ out)
{
    const int g  = blockIdx.y;
    const int b0 = blockIdx.x * 64;
    __shared__ float hs[32][65];
    __shared__ float ws[32][65];
    const int t = threadIdx.x;
    const int tx = (t % 16) * 4;
    const int ty = (t / 16) * 4;
    float acc[4][4] = {};

    for (int d0 = 0; d0 < DD; d0 += 32) {
        for (int i = t; i < 64 * 32; i += 256) {
            const int bi = i / 32, di = i % 32;
            hs[di][bi] = h[((size_t)(b0 + bi) * GG + g) * DD + d0 + di];
        }
        for (int i = t; i < 32 * 64; i += 256) {
            const int di = i / 64, fi = i % 64;
            ws[di][fi] = (fi < DUP) ? Wg[((size_t)g * DD + d0 + di) * DUP + fi] : 0.f;
        }
        __syncthreads();
        #pragma unroll
        for (int d = 0; d < 32; d++) {
            float rh[4], rb[4];
            #pragma unroll
            for (int i = 0; i < 4; i++) rh[i] = hs[d][ty + i];
            #pragma unroll
            for (int j = 0; j < 4; j++) rb[j] = ws[d][tx + j];
            #pragma unroll
            for (int i = 0; i < 4; i++)
                #pragma unroll
                for (int j = 0; j < 4; j++)
                    acc[i][j] += rh[i] * rb[j];
        }
        __syncthreads();
    }
    #pragma unroll
    for (int i = 0; i < 4; i++) {
        #pragma unroll
        for (int j = 0; j < 4; j++) {
            const int f = tx + j;
            if (f < DUP) {
                const int c = g * DUP + f;
                if (c < NCLS)
                    out[(size_t)(b0 + ty + i) * NCLS + c] = acc[i][j] + bg[c];
            }
        }
    }
}

// ---------------- launch -----------------------------------------------------
static float* sym(const void* s) { void* p = nullptr; cudaGetSymbolAddress(&p, s); return (float*)p; }
static __half* symh(const void* s) { void* p = nullptr; cudaGetSymbolAddress(&p, s); return (__half*)p; }

extern "C" void kernel_launch(void* const* d_in, const int* in_sizes, int n_in,
                              void* d_out, int out_size)
{
    (void)in_sizes; (void)n_in; (void)out_size;
    const float* x      = (const float*)d_in[0];
    const float* We     = (const float*)d_in[1];
    const float* be     = (const float*)d_in[2];
    const float* query  = (const float*)d_in[3];
    const float* Wq     = (const float*)d_in[4];
    const float* bq     = (const float*)d_in[5];
    const float* Wk     = (const float*)d_in[6];
    const float* bk     = (const float*)d_in[7];
    const float* Wv     = (const float*)d_in[8];
    const float* bv     = (const float*)d_in[9];
    const float* Wo     = (const float*)d_in[10];
    const float* bo     = (const float*)d_in[11];
    const float* g1     = (const float*)d_in[12];
    const float* beta1  = (const float*)d_in[13];
    const float* g2     = (const float*)d_in[14];
    const float* beta2  = (const float*)d_in[15];
    const float* g3     = (const float*)d_in[16];
    const float* beta3  = (const float*)d_in[17];
    const float* W1     = (const float*)d_in[18];
    const float* b1     = (const float*)d_in[19];
    const float* W2     = (const float*)d_in[20];
    const float* b2     = (const float*)d_in[21];
    const float* Wg     = (const float*)d_in[22];
    const float* bg     = (const float*)d_in[23];
    float* out = (float*)d_out;

    float *p_kv = sym(g_kv), *p_t1 = sym(g_t1), *p_q = sym(g_q);
    float *p_t2 = sym(g_t2), *p_h = sym(g_h), *p_bkv = sym(g_bkv);
    __half *p_xh = symh(g_xh), *p_mh = symh(g_mh), *p_t1h = symh(g_t1h);
    __half *p_aoh = symh(g_aoh), *p_oph = symh(g_oph), *p_t2h = symh(g_t2h);
    __half *p_ffh = symh(g_ffh), *p_f2h = symh(g_f2h);
    __half *pWe = symh(tWe), *pWq = symh(tWq), *pWkv = symh(tWkv);
    __half *pWo = symh(tWo), *pW1 = symh(tW1), *pW2 = symh(tW2);

    cudaFuncSetAttribute(tc_gemm<0, 0>, cudaFuncAttributeMaxDynamicSharedMemorySize, GEMM_SMEM);
    cudaFuncSetAttribute(tc_gemm<0, 1>, cudaFuncAttributeMaxDynamicSharedMemorySize, GEMM_SMEM);
    cudaFuncSetAttribute(tc_gemm<1, 1>, cudaFuncAttributeMaxDynamicSharedMemorySize, GEMM_SMEM);

    const float qscale = 0.10206207261596577f;  // 1/sqrt(96)

    // prep: weight transposes (fp16 [N,K]), input convert, bias concat
    transpose_half<<<dim3(DD / 32, CIN / 32), 256>>>(We, pWe, CIN, DD);
    convert_half<<<(BB * NN * CIN) / 1024, 256>>>(x, p_xh);
    transpose_half<<<dim3(DD / 32, DD / 32), 256>>>(Wq, pWq, DD, DD);
    transpose_half<<<dim3(DD / 32, DD / 32), 256>>>(Wk, pWkv, DD, DD);
    transpose_half<<<dim3(DD / 32, DD / 32), 256>>>(Wv, pWkv + (size_t)DD * DD, DD, DD);
    concat_bias<<<(DKV + 255) / 256, 256>>>(bk, bv, p_bkv);
    transpose_half<<<dim3(DD / 32, DD / 32), 256>>>(Wo, pWo, DD, DD);
    transpose_half<<<dim3(FF / 32, DD / 32), 256>>>(W1, pW1, DD, FF);
    transpose_half<<<dim3(DD / 32, FF / 32), 256>>>(W2, pW2, FF, DD);

    // t1 = LN(2*query) (+fp16); q = (t1@Wq + bq)/sqrt(96)
    ln_kernel<<<GG, 256>>>(query, nullptr, nullptr, g1, beta1, p_t1, p_t1h, 0);
    tc_gemm<0, 0><<<dim3(DD / 128, GG / 128), 128, GEMM_SMEM>>>(
        p_t1h, pWq, bq, p_q, nullptr, GG, DD, DD, qscale);

    // mem = relu(x @ We + be) -> fp16
    tc_gemm<1, 1><<<dim3(DD / 128, (BB * NN) / 128), 128, GEMM_SMEM>>>(
        p_xh, pWe, be, nullptr, p_mh, BB * NN, DD, CIN, 1.f);
    // fused K|V projection -> fp32 concat
    tc_gemm<0, 0><<<dim3(DKV / 128, (BB * NN) / 128), 128, GEMM_SMEM>>>(
        p_mh, pWkv, p_bkv, p_kv, nullptr, BB * NN, DKV, DD, 1.f);

    // fused attention -> fp16
    attn_kernel<<<dim3(HH, BB), 256>>>(p_q, p_kv, p_aoh);

    // output projection (fp16 out) + residual LN (t2 fp32 + fp16)
    tc_gemm<0, 1><<<dim3(DD / 128, (BB * GG) / 128), 128, GEMM_SMEM>>>(
        p_aoh, pWo, bo, nullptr, p_oph, BB * GG, DD, DD, 1.f);
    ln_kernel<<<BB * GG, 256>>>(nullptr, p_oph, p_t1, g2, beta2, p_t2, p_t2h, 1);

    // FFN: ff = relu(t2@W1+b1) -> fp16; ffn2 = ff@W2+b2 -> fp16
    tc_gemm<1, 1><<<dim3(FF / 128, (BB * GG) / 128), 128, GEMM_SMEM>>>(
        p_t2h, pW1, b1, nullptr, p_ffh, BB * GG, FF, DD, 1.f);
    tc_gemm<0, 1><<<dim3(DD / 128, (BB * GG) / 128), 128, GEMM_SMEM>>>(
        p_ffh, pW2, b2, nullptr, p_f2h, BB * GG, DD, FF, 1.f);
    ln_kernel<<<BB * GG, 256>>>(nullptr, p_f2h, p_t2, g3, beta3, p_h, nullptr, 2);

    // GroupFC
    groupfc_kernel<<<dim3(BB / 64, GG), 256>>>(p_h, Wg, bg, out);
}

// round 14
// speedup vs baseline: 1.2715x; 1.0793x over previous
#include <cuda_runtime.h>
#include <cuda_fp16.h>
#include <math.h>
#include <stdint.h>

// ---------------- problem constants ----------------
#define BB 128      // batch
#define NN 49       // spatial tokens
#define CIN 2048
#define GG 256      // query groups
#define DD 768      // model dim
#define HH 8        // heads
#define HD 96       // head dim
#define FF 2048
#define NCLS 12547
#define DUP 50
#define DKV 1536    // concat K|V projection width
#define NGRP 251    // groups that actually reach the 12547-class output

// ---------------- asm helpers (sm_80+ features only) -------------------------
__device__ __forceinline__ uint32_t smem_u32(const void* p) {
    uint32_t a;
    asm("{ .reg .u64 t; cvta.to.shared.u64 t, %1; cvt.u32.u64 %0, t; }" : "=r"(a) : "l"(p));
    return a;
}
#define CP16(dst, src) \
    asm volatile("cp.async.cg.shared.global [%0], [%1], 16;" :: "r"(dst), "l"(src))
#define CP_COMMIT() asm volatile("cp.async.commit_group;" ::: "memory")
#define CP_WAIT(n)  asm volatile("cp.async.wait_group %0;" :: "n"(n) : "memory")
#define LDSM4(r, addr) \
    asm volatile("ldmatrix.sync.aligned.m8n8.x4.shared.b16 {%0,%1,%2,%3}, [%4];" \
                 : "=r"((r)[0]), "=r"((r)[1]), "=r"((r)[2]), "=r"((r)[3]) : "r"(addr))
#define MMA_F16(c, a, b0, b1) \
    asm volatile("mma.sync.aligned.m16n8k16.row.col.f32.f16.f16.f32 " \
                 "{%0,%1,%2,%3},{%4,%5,%6,%7},{%8,%9},{%0,%1,%2,%3};" \
                 : "+f"((c)[0]), "+f"((c)[1]), "+f"((c)[2]), "+f"((c)[3]) \
                 : "r"((a)[0]), "r"((a)[1]), "r"((a)[2]), "r"((a)[3]), "r"(b0), "r"(b1))

// ---------------- scratch (device globals) -----------------------------------
// fp32
__device__ float g_t1   [GG * DD];
__device__ float g_q    [GG * DD];
__device__ float g_t2   [BB * GG * DD];
__device__ float g_bkv  [DKV];            // concat bias bk|bv
// fp16 activation operands
__device__ __half g_xh [BB * NN * CIN];
__device__ __half g_mh [BB * NN * DD];
__device__ __half g_t1h[GG * DD];
__device__ __half g_kvh[BB * NN * DKV];   // concat K|V (fp16)
__device__ __half g_aoh[BB * GG * DD];
__device__ __half g_oph[BB * GG * DD];    // Wo out (fp16)
__device__ __half g_t2h[BB * GG * DD];
__device__ __half g_ffh[BB * GG * FF];
__device__ __half g_f2h[BB * GG * DD];    // W2 out (fp16)
__device__ __half g_hh [BB * GG * DD];    // final LN out (fp16, groupfc input)
// transposed fp16 weights: [N,K]
__device__ __half tWe [DD * CIN];
__device__ __half tWq [DD * DD];
__device__ __half tWkv[DKV * DD];         // rows 0..767 = Wk^T, 768..1535 = Wv^T
__device__ __half tWo [DD * DD];
__device__ __half tW1 [FF * DD];
__device__ __half tW2 [DD * FF];
__device__ __half tWg [GG * 64 * DD];     // per-group [64(f,pad), 768(d)] fp16

// ---------------- weight transpose: W[K,N] fp32 -> [N,K] fp16 ----------------
__global__ __launch_bounds__(256)
void transpose_half(const float* __restrict__ W, __half* __restrict__ o,
                    int K, int N)
{
    __shared__ float tile[32][33];
    const int tx = threadIdx.x & 31, ty = threadIdx.x >> 5;
    const int kb = blockIdx.y * 32, nb = blockIdx.x * 32;
    #pragma unroll
    for (int i = 0; i < 4; i++)
        tile[ty + i * 8][tx] = W[(size_t)(kb + ty + i * 8) * N + nb + tx];
    __syncthreads();
    #pragma unroll
    for (int i = 0; i < 4; i++) {
        const int n = nb + ty + i * 8, k = kb + tx;
        o[(size_t)n * K + k] = __float2half(tile[tx][ty + i * 8]);
    }
}

// ---------------- Wg transpose: [G,768,50] fp32 -> [G,64,768] fp16 ------------
__global__ __launch_bounds__(256)
void transpose_wg(const float* __restrict__ Wg, __half* __restrict__ o)
{
    __shared__ float t[128 * DUP];       // 25.6 KB
    const int g = blockIdx.x, dc = blockIdx.y;   // dc: 0..5, 128 d-rows each
    const int tid = threadIdx.x;
    for (int i = tid; i < 128 * DUP; i += 256)
        t[i] = Wg[(size_t)g * DD * DUP + dc * 128 * DUP + i];
    __syncthreads();
    for (int j = tid; j < 64 * 128; j += 256) {
        const int f = j >> 7, d = j & 127;
        const float v = (f < DUP) ? t[d * DUP + f] : 0.f;
        o[(size_t)g * 64 * DD + (size_t)f * DD + dc * 128 + d] = __float2half(v);
    }
}

// ---------------- elementwise fp32 -> fp16 (for x) ---------------------------
__global__ __launch_bounds__(256)
void convert_half(const float* __restrict__ in, __half* __restrict__ out)
{
    const int i = (blockIdx.x * 256 + threadIdx.x) * 4;
    float4 v = *reinterpret_cast<const float4*>(in + i);
    __half2 a(__float2half(v.x), __float2half(v.y));
    __half2 b(__float2half(v.z), __float2half(v.w));
    *reinterpret_cast<__half2*>(out + i)     = a;
    *reinterpret_cast<__half2*>(out + i + 2) = b;
}

// ---------------- concat bk|bv ------------------------------------------------
__global__ void concat_bias(const float* __restrict__ bk, const float* __restrict__ bv,
                            float* __restrict__ o)
{
    const int i = blockIdx.x * 256 + threadIdx.x;
    if (i < DD) o[i] = bk[i];
    else if (i < DKV) o[i] = bv[i - DD];
}

// ---------------- fp16 single-pass tensor-core GEMM --------------------------
// C = act(alpha*(A @ B^T + bias));  A [M,K] fp16, B [N,K] fp16.
// BM=BN=128, BK=32; 4 warps x (64x64); 4-stage cp.async; single sync/iter.
#define LDSH 40                      // smem row stride in halves (80B, conflict-free)
#define TILE_B (128 * LDSH * 2)      // 10240B per tile
#define STAGE_B (2 * TILE_B)         // 20480B per stage (A, B)
#define NSTAGE 4
#define GEMM_SMEM (NSTAGE * STAGE_B) // 81920B

template <int RELU, int HOUT>
__global__ __launch_bounds__(128, 2)
void tc_gemm(const __half* __restrict__ A, const __half* __restrict__ B,
             const float* __restrict__ bias,
             float* __restrict__ Cf, __half* __restrict__ Ch,
             int M, int N, int K, float alpha)
{
    extern __shared__ __half sm[];
    const uint32_t sb = smem_u32(sm);
    const int tid = threadIdx.x, wid = tid >> 5, lane = tid & 31;
    const int wm = wid & 1, wn = wid >> 1;
    const int m0 = blockIdx.y * 128, n0 = blockIdx.x * 128;
    const int nst = K >> 5;

    auto load_stage = [&](int s, int buf) {
        const int k0 = s << 5;
        const uint32_t d0 = sb + buf * STAGE_B;
        #pragma unroll
        for (int i = 0; i < 8; i++) {
            const int isA = (i < 4);
            const int c = (i & 3) * 128 + tid;
            const int row = c >> 2, part = c & 3;
            const __half* src = (isA ? A + (size_t)(m0 + row) * K
                                     : B + (size_t)(n0 + row) * K) + k0 + part * 8;
            const uint32_t dst = d0 + (isA ? 0 : TILE_B) + row * (LDSH * 2) + part * 16;
            CP16(dst, src);
        }
        CP_COMMIT();
    };

    float acc[4][8][4];
    #pragma unroll
    for (int i = 0; i < 4; i++)
        #pragma unroll
        for (int j = 0; j < 8; j++)
            #pragma unroll
            for (int q = 0; q < 4; q++) acc[i][j][q] = 0.f;

    load_stage(0, 0);
    load_stage(1, 1);
    load_stage(2, 2);

    const int a_r = (lane & 15), a_c8 = (lane >> 4) * 8;
    const int b_r = ((lane >> 4) & 1) * 8 + (lane & 7);
    const int b_c8 = ((lane >> 3) & 1) * 8;

    int buf = 0;
    #pragma unroll 1
    for (int s = 0; s < nst; s++) {
        CP_WAIT(2);
        __syncthreads();
        const int pb = (buf + 3) & 3;
        if (s + 3 < nst) load_stage(s + 3, pb); else CP_COMMIT();

        const uint32_t ab = sb + buf * STAGE_B;
        const uint32_t bb = ab + TILE_B;

        uint32_t fA[2][4][4], fB[2][4][4];
        #pragma unroll
        for (int ks = 0; ks < 2; ks++) {
            const int kh = ks * 16;
            #pragma unroll
            for (int i = 0; i < 4; i++) {
                const uint32_t off = ((wm * 64 + i * 16 + a_r) * LDSH + kh + a_c8) * 2;
                LDSM4(fA[ks][i], ab + off);
            }
            #pragma unroll
            for (int j = 0; j < 4; j++) {
                const uint32_t off = ((wn * 64 + j * 16 + b_r) * LDSH + kh + b_c8) * 2;
                LDSM4(fB[ks][j], bb + off);
            }
        }
        #pragma unroll
        for (int ks = 0; ks < 2; ks++) {
            #pragma unroll
            for (int n = 0; n < 8; n++) {
                const int j = n >> 1, h = (n & 1) * 2;
                const uint32_t b0 = fB[ks][j][h], b1 = fB[ks][j][h + 1];
                #pragma unroll
                for (int i = 0; i < 4; i++)
                    MMA_F16(acc[i][n], fA[ks][i], b0, b1);
            }
        }
        buf = (buf + 1) & 3;
    }

    const int row0 = m0 + wm * 64 + (lane >> 2);
    const int col0 = n0 + wn * 64 + (lane & 3) * 2;
    #pragma unroll
    for (int i = 0; i < 4; i++) {
        #pragma unroll
        for (int j = 0; j < 8; j++) {
            const int r = row0 + i * 16;
            const int c = col0 + j * 8;
            const float b0 = bias[c], b1 = bias[c + 1];
            float v0 = alpha * (acc[i][j][0] + b0);
            float v1 = alpha * (acc[i][j][1] + b1);
            float v2 = alpha * (acc[i][j][2] + b0);
            float v3 = alpha * (acc[i][j][3] + b1);
            if (RELU) {
                v0 = fmaxf(v0, 0.f); v1 = fmaxf(v1, 0.f);
                v2 = fmaxf(v2, 0.f); v3 = fmaxf(v3, 0.f);
            }
            if (!HOUT) {
                *reinterpret_cast<float2*>(Cf + (size_t)r * N + c)       = make_float2(v0, v1);
                *reinterpret_cast<float2*>(Cf + (size_t)(r + 8) * N + c) = make_float2(v2, v3);
            } else {
                *reinterpret_cast<__half2*>(Ch + (size_t)r * N + c) =
                    __half2(__float2half(v0), __float2half(v1));
                *reinterpret_cast<__half2*>(Ch + (size_t)(r + 8) * N + c) =
                    __half2(__float2half(v2), __float2half(v3));
            }
        }
    }
}

// ---------------- LayerNorm over D=768 ---------------------------------------
// mode 0: x = 2*a32[row]; mode 1: x = a16 + r[row%G]; mode 2: x = a16 + r[row]
__global__ __launch_bounds__(256)
void ln_kernel(const float* __restrict__ a32, const __half* __restrict__ a16,
               const float* __restrict__ r,
               const float* __restrict__ gamma, const float* __restrict__ beta,
               float* __restrict__ out, __half* __restrict__ oh, int mode)
{
    const int row = blockIdx.x;
    const int t = threadIdx.x;

    float x[3];
    #pragma unroll
    for (int j = 0; j < 3; j++) {
        const int idx = t + j * 256;
        float val;
        if (mode == 0) {
            val = 2.f * a32[(size_t)row * DD + idx];
        } else {
            val = __half2float(a16[(size_t)row * DD + idx]);
            if (mode == 1) val += r[(size_t)(row & (GG - 1)) * DD + idx];
            else           val += r[(size_t)row * DD + idx];
        }
        x[j] = val;
    }
    float s1 = x[0] + x[1] + x[2];
    float s2 = x[0] * x[0] + x[1] * x[1] + x[2] * x[2];
    #pragma unroll
    for (int off = 16; off; off >>= 1) {
        s1 += __shfl_xor_sync(0xffffffffu, s1, off);
        s2 += __shfl_xor_sync(0xffffffffu, s2, off);
    }
    __shared__ float sh1[8], sh2[8];
    const int w = t >> 5, lane = t & 31;
    if (lane == 0) { sh1[w] = s1; sh2[w] = s2; }
    __syncthreads();
    float S1 = 0.f, S2 = 0.f;
    #pragma unroll
    for (int i = 0; i < 8; i++) { S1 += sh1[i]; S2 += sh2[i]; }
    const float mean = S1 * (1.f / (float)DD);
    const float var  = S2 * (1.f / (float)DD) - mean * mean;
    const float rstd = rsqrtf(var + 1e-5f);

    #pragma unroll
    for (int j = 0; j < 3; j++) {
        const int idx = t + j * 256;
        const float v = (x[j] - mean) * rstd * gamma[idx] + beta[idx];
        if (out) out[(size_t)row * DD + idx] = v;
        if (oh) oh[(size_t)row * DD + idx] = __float2half(v);
    }
}

// ---------------- fused cross-attention (fp16 kv concat), fp16 output --------
__global__ __launch_bounds__(256)
void attn_kernel(const float* __restrict__ q, const __half* __restrict__ kv,
                 __half* __restrict__ oh)
{
    __shared__ float ks[NN][HD];
    __shared__ float vs[NN][HD];
    const int h = blockIdx.x, b = blockIdx.y;
    const int t = threadIdx.x;

    for (int i = t; i < NN * HD; i += 256) {
        const int n = i / HD, d = i % HD;
        const size_t gi = ((size_t)(b * NN + n)) * DKV + h * HD + d;
        ks[n][d] = __half2float(kv[gi]);
        vs[n][d] = __half2float(kv[gi + DD]);
    }
    __syncthreads();

    const int g = t;
    float4 qv[HD / 4];
    const float4* qp = reinterpret_cast<const float4*>(q + (size_t)g * DD + h * HD);
    #pragma unroll
    for (int i = 0; i < HD / 4; i++) qv[i] = qp[i];

    float s[NN];
    #pragma unroll 7
    for (int n = 0; n < NN; n++) {
        const float4* kp = reinterpret_cast<const float4*>(ks[n]);
        float acc = 0.f;
        #pragma unroll
        for (int i = 0; i < HD / 4; i++) {
            float4 kk = kp[i];
            acc += qv[i].x * kk.x + qv[i].y * kk.y + qv[i].z * kk.z + qv[i].w * kk.w;
        }
        s[n] = acc;
    }
    float m = -1e30f;
    #pragma unroll
    for (int n = 0; n < NN; n++) m = fmaxf(m, s[n]);
    float sum = 0.f;
    #pragma unroll
    for (int n = 0; n < NN; n++) { s[n] = __expf(s[n] - m); sum += s[n]; }
    const float inv = 1.f / sum;

    const size_t ob = ((size_t)(b * GG + g)) * DD + h * HD;
    #pragma unroll
    for (int d4 = 0; d4 < HD / 4; d4++) {
        float4 acc = {0.f, 0.f, 0.f, 0.f};
        #pragma unroll 7
        for (int n = 0; n < NN; n++) {
            const float p = s[n];
            float4 vv = *reinterpret_cast<const float4*>(&vs[n][d4 * 4]);
            acc.x += p * vv.x; acc.y += p * vv.y; acc.z += p * vv.z; acc.w += p * vv.w;
        }
        acc.x *= inv; acc.y *= inv; acc.z *= inv; acc.w *= inv;
        *reinterpret_cast<__half2*>(oh + ob + d4 * 4) =
            __half2(__float2half(acc.x), __float2half(acc.y));
        *reinterpret_cast<__half2*>(oh + ob + d4 * 4 + 2) =
            __half2(__float2half(acc.z), __float2half(acc.w));
    }
}

// ---------------- GroupFC on tensor cores ------------------------------------
// One CTA per group g: C[128 b, 64 f] = h[:, g, :] @ Wt[g]^T;  K=768.
// 4 warps x (32x64); double-buffered cp.async.
#define GF_A_B (128 * LDSH * 2)          // 10240B
#define GF_B_B (64 * LDSH * 2)           // 5120B
#define GF_STAGE (GF_A_B + GF_B_B)       // 15360B
#define GF_SMEM (2 * GF_STAGE)           // 30720B

__global__ __launch_bounds__(128, 2)
void groupfc_tc(const __half* __restrict__ h, const __half* __restrict__ Wt,
                const float* __restrict__ bg, float* __restrict__ out)
{
    extern __shared__ __half sm[];
    const uint32_t sb = smem_u32(sm);
    const int g = blockIdx.x;
    const int tid = threadIdx.x, wid = tid >> 5, lane = tid & 31;

    auto load_stage = [&](int s, int buf) {
        const int k0 = s << 5;
        const uint32_t d0 = sb + buf * GF_STAGE;
        #pragma unroll
        for (int i = 0; i < 4; i++) {              // A: 128 rows x 4 chunks
            const int c = i * 128 + tid;
            const int row = c >> 2, part = c & 3;
            const __half* src = h + ((size_t)(row * GG + g)) * DD + k0 + part * 8;
            CP16(d0 + row * (LDSH * 2) + part * 16, src);
        }
        #pragma unroll
        for (int i = 0; i < 2; i++) {              // B: 64 rows x 4 chunks
            const int c = i * 128 + tid;
            const int row = c >> 2, part = c & 3;
            const __half* src = Wt + (size_t)g * 64 * DD + (size_t)row * DD + k0 + part * 8;
            CP16(d0 + GF_A_B + row * (LDSH * 2) + part * 16, src);
        }
        CP_COMMIT();
    };

    float acc[2][8][4];
    #pragma unroll
    for (int i = 0; i < 2; i++)
        #pragma unroll
        for (int j = 0; j < 8; j++)
            #pragma unroll
            for (int q = 0; q < 4; q++) acc[i][j][q] = 0.f;

    load_stage(0, 0);

    const int a_r = (lane & 15), a_c8 = (lane >> 4) * 8;
    const int b_r = ((lane >> 4) & 1) * 8 + (lane & 7);
    const int b_c8 = ((lane >> 3) & 1) * 8;
    const int nst = DD >> 5;   // 24

    #pragma unroll 1
    for (int s = 0; s < nst; s++) {
        if (s + 1 < nst) load_stage(s + 1, (s + 1) & 1); else CP_COMMIT();
        CP_WAIT(1);
        __syncthreads();
        const uint32_t ab = sb + (s & 1) * GF_STAGE;
        const uint32_t bb = ab + GF_A_B;

        #pragma unroll
        for (int ks = 0; ks < 2; ks++) {
            const int kh = ks * 16;
            uint32_t fA[2][4], fB[4][4];
            #pragma unroll
            for (int i = 0; i < 2; i++) {
                const uint32_t off = ((wid * 32 + i * 16 + a_r) * LDSH + kh + a_c8) * 2;
                LDSM4(fA[i], ab + off);
            }
            #pragma unroll
            for (int j = 0; j < 4; j++) {
                const uint32_t off = ((j * 16 + b_r) * LDSH + kh + b_c8) * 2;
                LDSM4(fB[j], bb + off);
            }
            #pragma unroll
            for (int n = 0; n < 8; n++) {
                const int j = n >> 1, hh = (n & 1) * 2;
                const uint32_t b0 = fB[j][hh], b1 = fB[j][hh + 1];
                #pragma unroll
                for (int i = 0; i < 2; i++)
                    MMA_F16(acc[i][n], fA[i], b0, b1);
            }
        }
        __syncthreads();
    }

    const int row0 = wid * 32 + (lane >> 2);
    const int col0 = (lane & 3) * 2;
    #pragma unroll
    for (int i = 0; i < 2; i++) {
        #pragma unroll
        for (int j = 0; j < 8; j++) {
            const int r0 = row0 + i * 16;
            const int f0 = col0 + j * 8;
            #pragma unroll
            for (int e = 0; e < 2; e++) {
                const int f = f0 + e;
                const int c = g * DUP + f;
                if (f < DUP && c < NCLS) {
                    out[(size_t)r0 * NCLS + c]       = acc[i][j][0 + e] + bg[c];
                    out[(size_t)(r0 + 8) * NCLS + c] = acc[i][j][2 + e] + bg[c];
                }
            }
        }
    }
}

// ---------------- launch -----------------------------------------------------
static float* sym(const void* s) { void* p = nullptr; cudaGetSymbolAddress(&p, s); return (float*)p; }
static __half* symh(const void* s) { void* p = nullptr; cudaGetSymbolAddress(&p, s); return (__half*)p; }

extern "C" void kernel_launch(void* const* d_in, const int* in_sizes, int n_in,
                              void* d_out, int out_size)
{
    (void)in_sizes; (void)n_in; (void)out_size;
    const float* x      = (const float*)d_in[0];
    const float* We     = (const float*)d_in[1];
    const float* be     = (const float*)d_in[2];
    const float* query  = (const float*)d_in[3];
    const float* Wq     = (const float*)d_in[4];
    const float* bq     = (const float*)d_in[5];
    const float* Wk     = (const float*)d_in[6];
    const float* bk     = (const float*)d_in[7];
    const float* Wv     = (const float*)d_in[8];
    const float* bv     = (const float*)d_in[9];
    const float* Wo     = (const float*)d_in[10];
    const float* bo     = (const float*)d_in[11];
    const float* g1     = (const float*)d_in[12];
    const float* beta1  = (const float*)d_in[13];
    const float* g2     = (const float*)d_in[14];
    const float* beta2  = (const float*)d_in[15];
    const float* g3     = (const float*)d_in[16];
    const float* beta3  = (const float*)d_in[17];
    const float* W1     = (const float*)d_in[18];
    const float* b1     = (const float*)d_in[19];
    const float* W2     = (const float*)d_in[20];
    const float* b2     = (const float*)d_in[21];
    const float* Wg     = (const float*)d_in[22];
    const float* bg     = (const float*)d_in[23];
    float* out = (float*)d_out;

    float *p_t1 = sym(g_t1), *p_q = sym(g_q), *p_t2 = sym(g_t2), *p_bkv = sym(g_bkv);
    __half *p_xh = symh(g_xh), *p_mh = symh(g_mh), *p_t1h = symh(g_t1h);
    __half *p_kvh = symh(g_kvh), *p_aoh = symh(g_aoh), *p_oph = symh(g_oph);
    __half *p_t2h = symh(g_t2h), *p_ffh = symh(g_ffh), *p_f2h = symh(g_f2h);
    __half *p_hh = symh(g_hh);
    __half *pWe = symh(tWe), *pWq = symh(tWq), *pWkv = symh(tWkv);
    __half *pWo = symh(tWo), *pW1 = symh(tW1), *pW2 = symh(tW2), *pWg = symh(tWg);

    cudaFuncSetAttribute(tc_gemm<0, 0>, cudaFuncAttributeMaxDynamicSharedMemorySize, GEMM_SMEM);
    cudaFuncSetAttribute(tc_gemm<0, 1>, cudaFuncAttributeMaxDynamicSharedMemorySize, GEMM_SMEM);
    cudaFuncSetAttribute(tc_gemm<1, 1>, cudaFuncAttributeMaxDynamicSharedMemorySize, GEMM_SMEM);
    cudaFuncSetAttribute(groupfc_tc, cudaFuncAttributeMaxDynamicSharedMemorySize, GF_SMEM);

    const float qscale = 0.10206207261596577f;  // 1/sqrt(96)

    // prep: weight transposes (fp16 [N,K]), input convert, bias concat
    transpose_half<<<dim3(DD / 32, CIN / 32), 256>>>(We, pWe, CIN, DD);
    convert_half<<<(BB * NN * CIN) / 1024, 256>>>(x, p_xh);
    transpose_half<<<dim3(DD / 32, DD / 32), 256>>>(Wq, pWq, DD, DD);
    transpose_half<<<dim3(DD / 32, DD / 32), 256>>>(Wk, pWkv, DD, DD);
    transpose_half<<<dim3(DD / 32, DD / 32), 256>>>(Wv, pWkv + (size_t)DD * DD, DD, DD);
    concat_bias<<<(DKV + 255) / 256, 256>>>(bk, bv, p_bkv);
    transpose_half<<<dim3(DD / 32, DD / 32), 256>>>(Wo, pWo, DD, DD);
    transpose_half<<<dim3(FF / 32, DD / 32), 256>>>(W1, pW1, DD, FF);
    transpose_half<<<dim3(DD / 32, FF / 32), 256>>>(W2, pW2, FF, DD);
    transpose_wg<<<dim3(NGRP, DD / 128), 256>>>(Wg, pWg);

    // t1 = LN(2*query) (+fp16); q = (t1@Wq + bq)/sqrt(96)
    ln_kernel<<<GG, 256>>>(query, nullptr, nullptr, g1, beta1, p_t1, p_t1h, 0);
    tc_gemm<0, 0><<<dim3(DD / 128, GG / 128), 128, GEMM_SMEM>>>(
        p_t1h, pWq, bq, p_q, nullptr, GG, DD, DD, qscale);

    // mem = relu(x @ We + be) -> fp16
    tc_gemm<1, 1><<<dim3(DD / 128, (BB * NN) / 128), 128, GEMM_SMEM>>>(
        p_xh, pWe, be, nullptr, p_mh, BB * NN, DD, CIN, 1.f);
    // fused K|V projection -> fp16 concat
    tc_gemm<0, 1><<<dim3(DKV / 128, (BB * NN) / 128), 128, GEMM_SMEM>>>(
        p_mh, pWkv, p_bkv, nullptr, p_kvh, BB * NN, DKV, DD, 1.f);

    // fused attention -> fp16
    attn_kernel<<<dim3(HH, BB), 256>>>(p_q, p_kvh, p_aoh);

    // output projection (fp16 out) + residual LN (t2 fp32 + fp16)
    tc_gemm<0, 1><<<dim3(DD / 128, (BB * GG) / 128), 128, GEMM_SMEM>>>(
        p_aoh, pWo, bo, nullptr, p_oph, BB * GG, DD, DD, 1.f);
    ln_kernel<<<BB * GG, 256>>>(nullptr, p_oph, p_t1, g2, beta2, p_t2, p_t2h, 1);

    // FFN: ff = relu(t2@W1+b1) -> fp16; ffn2 = ff@W2+b2 -> fp16
    tc_gemm<1, 1><<<dim3(FF / 128, (BB * GG) / 128), 128, GEMM_SMEM>>>(
        p_t2h, pW1, b1, nullptr, p_ffh, BB * GG, FF, DD, 1.f);
    tc_gemm<0, 1><<<dim3(DD / 128, (BB * GG) / 128), 128, GEMM_SMEM>>>(
        p_ffh, pW2, b2, nullptr, p_f2h, BB * GG, DD, FF, 1.f);
    // h = LN(t2 + ffn2) -> fp16 only
    ln_kernel<<<BB * GG, 256>>>(nullptr, p_f2h, p_t2, g3, beta3, nullptr, p_hh, 2);

    // GroupFC on tensor cores (groups 251..255 never reach the output)
    groupfc_tc<<<NGRP, 128, GF_SMEM>>>(p_hh, pWg, bg, out);
}